// round 4
// baseline (speedup 1.0000x reference)
#include <cuda_runtime.h>
#include <math.h>

// Problem constants
#define BB   4
#define TT   2048
#define DD   1024
#define HH   16
#define HD   64
#define BT   (BB * TT)        // 8192
#define D3   (3 * DD)         // 3072

// Scratch (allocation-free rule: __device__ globals)
__device__ float g_qkv[BT * D3];   // [8192][3072]  Q|K|V packed
__device__ float g_att[BT * DD];   // [8192][1024]  attention output

// ---------------------------------------------------------------------------
// Generic fp32 GEMM: C[M,N] = A[M,K] @ W[K,N], all row-major.
// 128x128 block tile, BK=8, 256 threads, 8x8 per-thread register tile.
// M given by gridDim.y*128, N by gridDim.x*128. M,N,K all multiples of tile.
// ---------------------------------------------------------------------------
__global__ __launch_bounds__(256)
void gemm128x128(const float* __restrict__ A, const float* __restrict__ W,
                 float* __restrict__ C, int N, int K) {
    __shared__ float As[8][132];   // transposed A tile, padded (conflict-free)
    __shared__ float Bs[8][128];

    const int tid  = threadIdx.x;
    const int tx   = tid & 15;          // 0..15  (N dir)
    const int ty   = tid >> 4;          // 0..15  (M dir)
    const int arow = tid >> 1;          // 0..127
    const int acol = (tid & 1) * 4;     // 0 or 4
    const int brow = tid >> 5;          // 0..7
    const int bcol = (tid & 31) * 4;    // 0..124

    const float* Ap = A + (size_t)(blockIdx.y * 128 + arow) * K + acol;
    const float* Bp = W + (size_t)brow * N + blockIdx.x * 128 + bcol;

    float acc[8][8];
    #pragma unroll
    for (int i = 0; i < 8; i++)
        #pragma unroll
        for (int j = 0; j < 8; j++) acc[i][j] = 0.0f;

    for (int kt = 0; kt < K; kt += 8) {
        float4 av = *(const float4*)(Ap + kt);
        float4 bv = *(const float4*)(Bp + (size_t)kt * N);
        As[acol + 0][arow] = av.x;
        As[acol + 1][arow] = av.y;
        As[acol + 2][arow] = av.z;
        As[acol + 3][arow] = av.w;
        *(float4*)&Bs[brow][bcol] = bv;
        __syncthreads();

        #pragma unroll
        for (int k = 0; k < 8; k++) {
            float a[8], b[8];
            *(float4*)&a[0] = *(const float4*)&As[k][ty * 8];
            *(float4*)&a[4] = *(const float4*)&As[k][ty * 8 + 4];
            *(float4*)&b[0] = *(const float4*)&Bs[k][tx * 8];
            *(float4*)&b[4] = *(const float4*)&Bs[k][tx * 8 + 4];
            #pragma unroll
            for (int i = 0; i < 8; i++)
                #pragma unroll
                for (int j = 0; j < 8; j++)
                    acc[i][j] += a[i] * b[j];
        }
        __syncthreads();
    }

    float* Cp = C + (size_t)(blockIdx.y * 128 + ty * 8) * N + blockIdx.x * 128 + tx * 8;
    #pragma unroll
    for (int i = 0; i < 8; i++) {
        *(float4*)(Cp + (size_t)i * N)     = make_float4(acc[i][0], acc[i][1], acc[i][2], acc[i][3]);
        *(float4*)(Cp + (size_t)i * N + 4) = make_float4(acc[i][4], acc[i][5], acc[i][6], acc[i][7]);
    }
}

// ---------------------------------------------------------------------------
// Flash attention (no 1/sqrt(hd) scaling, matching reference).
// grid: (T/128, H, B), block: 256 threads.
// Q block = 128 rows, KV tile = 128, hd = 64.
// Per-thread: 8 q-rows (r = 8*ty+i) x 8 s-cols (c = 8*tx+j); O tile 8x4.
// smem: Qs[128][64] natural | KP: Kt[64][128] xor-swizzled, reused as Ps[128][128] | Vs[128][64] natural.
// ---------------------------------------------------------------------------
__global__ __launch_bounds__(256)
void attn_kernel(const float* __restrict__ qkv, float* __restrict__ outp) {
    extern __shared__ float sm[];
    float* Qs = sm;                 // 8192 floats
    float* KP = sm + 8192;          // 16384 floats (Kt 8192 + P overflow)
    float* Vs = sm + 24576;         // 8192 floats

    const int tid = threadIdx.x;
    const int tx  = tid & 15;
    const int ty  = tid >> 4;
    const int qb  = blockIdx.x;
    const int h   = blockIdx.y;
    const int b   = blockIdx.z;
    const int t0  = qb * 128;
    const size_t rowbase = (size_t)b * TT * D3 + (size_t)h * HD;

    // Load Q tile [128][64] (coalesced: 2 rows x 256B per warp)
    #pragma unroll
    for (int it = 0; it < 8; it++) {
        int tl = ty + it * 16;
        float4 v = *(const float4*)(qkv + rowbase + (size_t)(t0 + tl) * D3 + tx * 4);
        *(float4*)&Qs[tl * 64 + tx * 4] = v;
    }

    float O[8][4];
    float m_i[8], l_i[8];
    #pragma unroll
    for (int i = 0; i < 8; i++) {
        m_i[i] = -1e30f;
        l_i[i] = 0.0f;
        #pragma unroll
        for (int n = 0; n < 4; n++) O[i][n] = 0.0f;
    }

    for (int kt = 0; kt < TT / 128; kt++) {
        __syncthreads();   // prior PV done with Ps/Vs; also orders first Q-load
        // Load K (transposed + xor-swizzled) and V (natural)
        #pragma unroll
        for (int it = 0; it < 8; it++) {
            int tl = ty + it * 16;
            size_t grow = rowbase + (size_t)(kt * 128 + tl) * D3;
            float4 k4 = *(const float4*)(qkv + grow + DD     + tx * 4);
            float4 v4 = *(const float4*)(qkv + grow + 2 * DD + tx * 4);
            // Kt element (kk=d, c=tl) at: kk*128 + ((c>>2 ^ kk>>2)&31)*4 + (c&3)
            int g = (((tl >> 2) ^ tx) & 31) * 4 + (tl & 3);
            KP[(4 * tx + 0) * 128 + g] = k4.x;
            KP[(4 * tx + 1) * 128 + g] = k4.y;
            KP[(4 * tx + 2) * 128 + g] = k4.z;
            KP[(4 * tx + 3) * 128 + g] = k4.w;
            *(float4*)&Vs[tl * 64 + tx * 4] = v4;
        }
        __syncthreads();

        // S = Q @ K^T  (acc[8][8])
        float acc[8][8];
        #pragma unroll
        for (int i = 0; i < 8; i++)
            #pragma unroll
            for (int j = 0; j < 8; j++) acc[i][j] = 0.0f;

        #pragma unroll 1
        for (int kk = 0; kk < 64; kk += 4) {
            float qf[8][4];
            #pragma unroll
            for (int i = 0; i < 8; i++) {
                float4 q4 = *(const float4*)&Qs[(ty * 8 + i) * 64 + kk];
                qf[i][0] = q4.x; qf[i][1] = q4.y; qf[i][2] = q4.z; qf[i][3] = q4.w;
            }
            const int gs = (kk >> 2);
            const int g0 = (((2 * tx)     ^ gs) & 31) * 4;
            const int g1 = (((2 * tx + 1) ^ gs) & 31) * 4;
            #pragma unroll
            for (int m = 0; m < 4; m++) {
                int row = (kk + m) * 128;
                float4 k0 = *(const float4*)&KP[row + g0];
                float4 k1 = *(const float4*)&KP[row + g1];
                float kf[8] = {k0.x, k0.y, k0.z, k0.w, k1.x, k1.y, k1.z, k1.w};
                #pragma unroll
                for (int i = 0; i < 8; i++)
                    #pragma unroll
                    for (int j = 0; j < 8; j++)
                        acc[i][j] += qf[i][m] * kf[j];
            }
        }
        __syncthreads();   // everyone done reading Kt before P overwrites it

        // Online softmax (rows owned by 16 tx-lanes; width-16 shfl reductions)
        #pragma unroll
        for (int i = 0; i < 8; i++) {
            float rmax = acc[i][0];
            #pragma unroll
            for (int j = 1; j < 8; j++) rmax = fmaxf(rmax, acc[i][j]);
            #pragma unroll
            for (int s = 8; s > 0; s >>= 1)
                rmax = fmaxf(rmax, __shfl_xor_sync(0xffffffffu, rmax, s, 16));

            float mnew  = fmaxf(m_i[i], rmax);
            float scale = __expf(m_i[i] - mnew);
            float p[8], rsum = 0.0f;
            #pragma unroll
            for (int j = 0; j < 8; j++) { p[j] = __expf(acc[i][j] - mnew); rsum += p[j]; }
            #pragma unroll
            for (int s = 8; s > 0; s >>= 1)
                rsum += __shfl_xor_sync(0xffffffffu, rsum, s, 16);

            l_i[i] = l_i[i] * scale + rsum;
            m_i[i] = mnew;
            #pragma unroll
            for (int n = 0; n < 4; n++) O[i][n] *= scale;

            *(float4*)&KP[(ty * 8 + i) * 128 + tx * 8]     = make_float4(p[0], p[1], p[2], p[3]);
            *(float4*)&KP[(ty * 8 + i) * 128 + tx * 8 + 4] = make_float4(p[4], p[5], p[6], p[7]);
        }
        __syncthreads();   // Ps ready

        // O += P @ V
        #pragma unroll 1
        for (int j4 = 0; j4 < 128; j4 += 4) {
            float pf[8][4];
            #pragma unroll
            for (int i = 0; i < 8; i++) {
                float4 p4 = *(const float4*)&KP[(ty * 8 + i) * 128 + j4];
                pf[i][0] = p4.x; pf[i][1] = p4.y; pf[i][2] = p4.z; pf[i][3] = p4.w;
            }
            float vf[4][4];
            #pragma unroll
            for (int m = 0; m < 4; m++) {
                float4 v4 = *(const float4*)&Vs[(j4 + m) * 64 + tx * 4];
                vf[m][0] = v4.x; vf[m][1] = v4.y; vf[m][2] = v4.z; vf[m][3] = v4.w;
            }
            #pragma unroll
            for (int i = 0; i < 8; i++)
                #pragma unroll
                for (int m = 0; m < 4; m++)
                    #pragma unroll
                    for (int n = 0; n < 4; n++)
                        O[i][n] += pf[i][m] * vf[m][n];
        }
    }

    // Normalize and write out: [B,T,H,hd] -> [BT][1024]
    #pragma unroll
    for (int i = 0; i < 8; i++) {
        float inv = 1.0f / l_i[i];
        size_t orow = (size_t)(b * TT + t0 + ty * 8 + i) * DD + h * HD + tx * 4;
        *(float4*)(outp + orow) = make_float4(O[i][0] * inv, O[i][1] * inv,
                                              O[i][2] * inv, O[i][3] * inv);
    }
}

// ---------------------------------------------------------------------------
// kernel_launch: x -> qkv GEMM -> flash attention -> proj GEMM
// ---------------------------------------------------------------------------
extern "C" void kernel_launch(void* const* d_in, const int* in_sizes, int n_in,
                              void* d_out, int out_size) {
    const float* x      = (const float*)d_in[0];   // [4,2048,1024]
    const float* w_qkv  = (const float*)d_in[1];   // [1024,3072]
    const float* w_proj = (const float*)d_in[2];   // [1024,1024]
    float* out = (float*)d_out;                    // [4,2048,1024]

    float *qkv_p, *att_p;
    cudaGetSymbolAddress((void**)&qkv_p, g_qkv);
    cudaGetSymbolAddress((void**)&att_p, g_att);

    cudaFuncSetAttribute(attn_kernel, cudaFuncAttributeMaxDynamicSharedMemorySize, 131072);

    // 1) QKV projection: [8192,1024] @ [1024,3072]
    gemm128x128<<<dim3(D3 / 128, BT / 128), 256>>>(x, w_qkv, qkv_p, D3, DD);
    // 2) Attention
    attn_kernel<<<dim3(TT / 128, HH, BB), 256, 131072>>>(qkv_p, att_p);
    // 3) Output projection: [8192,1024] @ [1024,1024]
    gemm128x128<<<dim3(DD / 128, BT / 128), 256>>>(att_p, w_proj, out, DD, DD);
}

// round 6
// speedup vs baseline: 1.3803x; 1.3803x over previous
#include <cuda_runtime.h>
#include <cuda_bf16.h>
#include <math.h>
#include <stdint.h>

// Problem constants
#define BB   4
#define TT   2048
#define DD   1024
#define HH   16
#define HD   64
#define BT   (BB * TT)        // 8192
#define D3   (3 * DD)         // 3072

// Scratch (allocation-free rule: __device__ globals)
__device__ float g_qkv[BT * D3];            // [8192][3072] Q|K|V packed (fp32)
__device__ float g_att[BT * DD];            // [8192][1024] attention output (fp32)
__device__ __nv_bfloat16 g_ah[BT * DD];     // activation hi (x, then att)
__device__ __nv_bfloat16 g_al[BT * DD];     // activation lo
__device__ __nv_bfloat16 g_bh[DD * D3];     // weight^T hi (max size for qkv)
__device__ __nv_bfloat16 g_bl[DD * D3];     // weight^T lo

__device__ __forceinline__ uint32_t smem_u32(const void* p) {
    uint32_t a;
    asm("{ .reg .u64 t; cvta.to.shared.u64 t, %1; cvt.u32.u64 %0, t; }" : "=r"(a) : "l"(p));
    return a;
}

#define CP_ASYNC16(saddr, gptr) \
    asm volatile("cp.async.cg.shared.global [%0], [%1], 16;" :: "r"(saddr), "l"(gptr) : "memory")
#define CP_COMMIT() asm volatile("cp.async.commit_group;" ::: "memory")
#define CP_WAIT1()  asm volatile("cp.async.wait_group 1;" ::: "memory")
#define CP_WAIT0()  asm volatile("cp.async.wait_group 0;" ::: "memory")

__device__ __forceinline__ void mma16816(float* c, const uint32_t* a, const uint32_t* b) {
    asm volatile(
        "mma.sync.aligned.m16n8k16.row.col.f32.bf16.bf16.f32 "
        "{%0,%1,%2,%3}, {%4,%5,%6,%7}, {%8,%9}, {%0,%1,%2,%3};"
        : "+f"(c[0]), "+f"(c[1]), "+f"(c[2]), "+f"(c[3])
        : "r"(a[0]), "r"(a[1]), "r"(a[2]), "r"(a[3]), "r"(b[0]), "r"(b[1]));
}

// ---------------------------------------------------------------------------
// fp32 -> (hi, lo) bf16 split, elementwise. n must be multiple of 4.
// ---------------------------------------------------------------------------
__global__ __launch_bounds__(256)
void split_kernel(const float* __restrict__ in, __nv_bfloat16* __restrict__ hi,
                  __nv_bfloat16* __restrict__ lo, int n) {
    int i = (blockIdx.x * 256 + threadIdx.x) * 4;
    if (i >= n) return;
    float4 v = *(const float4*)(in + i);
    __nv_bfloat16 h0 = __float2bfloat16(v.x), h1 = __float2bfloat16(v.y);
    __nv_bfloat16 h2 = __float2bfloat16(v.z), h3 = __float2bfloat16(v.w);
    __nv_bfloat16 l0 = __float2bfloat16(v.x - __bfloat162float(h0));
    __nv_bfloat16 l1 = __float2bfloat16(v.y - __bfloat162float(h1));
    __nv_bfloat16 l2 = __float2bfloat16(v.z - __bfloat162float(h2));
    __nv_bfloat16 l3 = __float2bfloat16(v.w - __bfloat162float(h3));
    __nv_bfloat162* hp = (__nv_bfloat162*)(hi + i);
    __nv_bfloat162* lp = (__nv_bfloat162*)(lo + i);
    hp[0] = __nv_bfloat162(h0, h1); hp[1] = __nv_bfloat162(h2, h3);
    lp[0] = __nv_bfloat162(l0, l1); lp[1] = __nv_bfloat162(l2, l3);
}

// ---------------------------------------------------------------------------
// W [K,N] fp32 row-major -> Wt hi/lo [N,K] bf16 row-major (transpose + split)
// grid (N/32, K/32), block 256 (32x8)
// ---------------------------------------------------------------------------
__global__ __launch_bounds__(256)
void transpose_split(const float* __restrict__ W, __nv_bfloat16* __restrict__ Th,
                     __nv_bfloat16* __restrict__ Tl, int K, int N) {
    __shared__ float t[32][33];
    const int k0 = blockIdx.y * 32, n0 = blockIdx.x * 32;
    const int tx = threadIdx.x & 31, ty = threadIdx.x >> 5;
    #pragma unroll
    for (int i = 0; i < 32; i += 8)
        t[ty + i][tx] = W[(size_t)(k0 + ty + i) * N + n0 + tx];
    __syncthreads();
    #pragma unroll
    for (int i = 0; i < 32; i += 8) {
        float v = t[tx][ty + i];          // = W[k0+tx][n0+ty+i]
        __nv_bfloat16 h = __float2bfloat16(v);
        size_t o = (size_t)(n0 + ty + i) * K + k0 + tx;
        Th[o] = h;
        Tl[o] = __float2bfloat16(v - __bfloat162float(h));
    }
}

// ---------------------------------------------------------------------------
// mma.sync bf16 split-GEMM: C[M,N] = A @ W  (fp32-equivalent precision)
//   Ah/Al: [M,K] bf16 row-major (K-major)
//   Bh/Bl: [N,K] bf16 row-major (W transposed, K-major)
// 128x128 CTA tile, 256 threads (8 warps, 4x2), K-chunk 32, cp.async 2-stage.
// smem per stage: 4 tiles of [128][40] bf16 (pad 32->40, conflict-free frags).
// ---------------------------------------------------------------------------
#define TS   (128 * 40)                // bf16 elems per tile
#define STG  (4 * TS)                  // elems per stage (Ah|Al|Bh|Bl)

__global__ __launch_bounds__(256)
void gemm_mma(const __nv_bfloat16* __restrict__ Ah, const __nv_bfloat16* __restrict__ Al,
              const __nv_bfloat16* __restrict__ Bh, const __nv_bfloat16* __restrict__ Bl,
              float* __restrict__ C, int N, int K) {
    extern __shared__ __align__(16) __nv_bfloat16 sm[];   // 2 * STG elems = 81920 B
    const uint32_t sb = smem_u32(sm);

    const int tid  = threadIdx.x;
    const int wid  = tid >> 5;
    const int lane = tid & 31;
    const int g    = lane >> 2;          // 0..7
    const int tg   = lane & 3;           // 0..3
    const int wm   = (wid >> 1) * 32;    // warp M offset (0,32,64,96)
    const int wn   = (wid & 1) * 64;     // warp N offset (0,64)
    const int m0   = blockIdx.y * 128;
    const int n0   = blockIdx.x * 128;

    float acc[2][8][4];
    #pragma unroll
    for (int i = 0; i < 2; i++)
        #pragma unroll
        for (int j = 0; j < 8; j++)
            #pragma unroll
            for (int c = 0; c < 4; c++) acc[i][j][c] = 0.0f;

    // Loader mapping: 512 16B-chunks per tile; thread does chunks tid, tid+256.
    const int KT = K >> 5;               // 32-wide K chunks

    // ---- issue loads for a stage ----
    auto issue = [&](int stage, int kt) {
        const int k0 = kt * 32;
        uint32_t sbase = sb + stage * STG * 2;   // bytes
        #pragma unroll
        for (int h = 0; h < 2; h++) {
            int c   = tid + h * 256;             // 0..511
            int row = c >> 2;                    // 0..127
            int cc  = c & 3;                     // 16B chunk in row
            size_t ga = (size_t)(m0 + row) * K + k0 + cc * 8;
            size_t gb = (size_t)(n0 + row) * K + k0 + cc * 8;
            uint32_t so = (uint32_t)(row * 80 + cc * 16);   // bytes in tile
            CP_ASYNC16(sbase + so,                Ah + ga);
            CP_ASYNC16(sbase + TS * 2 + so,       Al + ga);
            CP_ASYNC16(sbase + TS * 4 + so,       Bh + gb);
            CP_ASYNC16(sbase + TS * 6 + so,       Bl + gb);
        }
        CP_COMMIT();
    };

    issue(0, 0);

    for (int kt = 0; kt < KT; kt++) {
        const int stage = kt & 1;
        if (kt + 1 < KT) { issue(stage ^ 1, kt + 1); CP_WAIT1(); }
        else             { CP_WAIT0(); }
        __syncthreads();

        const __nv_bfloat16* sAh = sm + stage * STG;
        const __nv_bfloat16* sAl = sAh + TS;
        const __nv_bfloat16* sBh = sAh + 2 * TS;
        const __nv_bfloat16* sBl = sAh + 3 * TS;

        #pragma unroll
        for (int ks = 0; ks < 32; ks += 16) {
            uint32_t ah[2][4], al[2][4], bh[8][2], bl[8][2];
            #pragma unroll
            for (int i = 0; i < 2; i++) {
                int r = wm + i * 16 + g;
                int cA = ks + tg * 2;
                ah[i][0] = *(const uint32_t*)&sAh[r * 40 + cA];
                ah[i][1] = *(const uint32_t*)&sAh[(r + 8) * 40 + cA];
                ah[i][2] = *(const uint32_t*)&sAh[r * 40 + cA + 8];
                ah[i][3] = *(const uint32_t*)&sAh[(r + 8) * 40 + cA + 8];
                al[i][0] = *(const uint32_t*)&sAl[r * 40 + cA];
                al[i][1] = *(const uint32_t*)&sAl[(r + 8) * 40 + cA];
                al[i][2] = *(const uint32_t*)&sAl[r * 40 + cA + 8];
                al[i][3] = *(const uint32_t*)&sAl[(r + 8) * 40 + cA + 8];
            }
            #pragma unroll
            for (int j = 0; j < 8; j++) {
                int rn = wn + j * 8 + g;
                int cB = ks + tg * 2;
                bh[j][0] = *(const uint32_t*)&sBh[rn * 40 + cB];
                bh[j][1] = *(const uint32_t*)&sBh[rn * 40 + cB + 8];
                bl[j][0] = *(const uint32_t*)&sBl[rn * 40 + cB];
                bl[j][1] = *(const uint32_t*)&sBl[rn * 40 + cB + 8];
            }
            #pragma unroll
            for (int i = 0; i < 2; i++)
                #pragma unroll
                for (int j = 0; j < 8; j++) {
                    mma16816(acc[i][j], ah[i], bh[j]);   // Ah*Bh
                    mma16816(acc[i][j], ah[i], bl[j]);   // Ah*Bl
                    mma16816(acc[i][j], al[i], bh[j]);   // Al*Bh
                }
        }
        __syncthreads();
    }

    // Epilogue: c0=(g, tg*2), c1=(g, tg*2+1), c2=(g+8, ...), c3
    #pragma unroll
    for (int i = 0; i < 2; i++) {
        int r0 = m0 + wm + i * 16 + g;
        #pragma unroll
        for (int j = 0; j < 8; j++) {
            int cc = n0 + wn + j * 8 + tg * 2;
            *(float2*)(C + (size_t)r0 * N + cc)       = make_float2(acc[i][j][0], acc[i][j][1]);
            *(float2*)(C + (size_t)(r0 + 8) * N + cc) = make_float2(acc[i][j][2], acc[i][j][3]);
        }
    }
}

// ---------------------------------------------------------------------------
// Flash attention (fp32, unchanged from passing round).
// grid: (T/128, H, B), block: 256 threads; 128KB dynamic smem.
// ---------------------------------------------------------------------------
__global__ __launch_bounds__(256)
void attn_kernel(const float* __restrict__ qkv, float* __restrict__ outp) {
    extern __shared__ float smf[];
    float* Qs = smf;                 // 8192 floats
    float* KP = smf + 8192;          // 16384 floats (Kt 8192 + P overflow)
    float* Vs = smf + 24576;         // 8192 floats

    const int tid = threadIdx.x;
    const int tx  = tid & 15;
    const int ty  = tid >> 4;
    const int qb  = blockIdx.x;
    const int h   = blockIdx.y;
    const int b   = blockIdx.z;
    const int t0  = qb * 128;
    const size_t rowbase = (size_t)b * TT * D3 + (size_t)h * HD;

    #pragma unroll
    for (int it = 0; it < 8; it++) {
        int tl = ty + it * 16;
        float4 v = *(const float4*)(qkv + rowbase + (size_t)(t0 + tl) * D3 + tx * 4);
        *(float4*)&Qs[tl * 64 + tx * 4] = v;
    }

    float O[8][4];
    float m_i[8], l_i[8];
    #pragma unroll
    for (int i = 0; i < 8; i++) {
        m_i[i] = -1e30f;
        l_i[i] = 0.0f;
        #pragma unroll
        for (int n = 0; n < 4; n++) O[i][n] = 0.0f;
    }

    for (int kt = 0; kt < TT / 128; kt++) {
        __syncthreads();
        #pragma unroll
        for (int it = 0; it < 8; it++) {
            int tl = ty + it * 16;
            size_t grow = rowbase + (size_t)(kt * 128 + tl) * D3;
            float4 k4 = *(const float4*)(qkv + grow + DD     + tx * 4);
            float4 v4 = *(const float4*)(qkv + grow + 2 * DD + tx * 4);
            int g = (((tl >> 2) ^ tx) & 31) * 4 + (tl & 3);
            KP[(4 * tx + 0) * 128 + g] = k4.x;
            KP[(4 * tx + 1) * 128 + g] = k4.y;
            KP[(4 * tx + 2) * 128 + g] = k4.z;
            KP[(4 * tx + 3) * 128 + g] = k4.w;
            *(float4*)&Vs[tl * 64 + tx * 4] = v4;
        }
        __syncthreads();

        float acc[8][8];
        #pragma unroll
        for (int i = 0; i < 8; i++)
            #pragma unroll
            for (int j = 0; j < 8; j++) acc[i][j] = 0.0f;

        #pragma unroll 1
        for (int kk = 0; kk < 64; kk += 4) {
            float qf[8][4];
            #pragma unroll
            for (int i = 0; i < 8; i++) {
                float4 q4 = *(const float4*)&Qs[(ty * 8 + i) * 64 + kk];
                qf[i][0] = q4.x; qf[i][1] = q4.y; qf[i][2] = q4.z; qf[i][3] = q4.w;
            }
            const int gs = (kk >> 2);
            const int g0 = (((2 * tx)     ^ gs) & 31) * 4;
            const int g1 = (((2 * tx + 1) ^ gs) & 31) * 4;
            #pragma unroll
            for (int m = 0; m < 4; m++) {
                int row = (kk + m) * 128;
                float4 k0 = *(const float4*)&KP[row + g0];
                float4 k1 = *(const float4*)&KP[row + g1];
                float kf[8] = {k0.x, k0.y, k0.z, k0.w, k1.x, k1.y, k1.z, k1.w};
                #pragma unroll
                for (int i = 0; i < 8; i++)
                    #pragma unroll
                    for (int j = 0; j < 8; j++)
                        acc[i][j] += qf[i][m] * kf[j];
            }
        }
        __syncthreads();

        #pragma unroll
        for (int i = 0; i < 8; i++) {
            float rmax = acc[i][0];
            #pragma unroll
            for (int j = 1; j < 8; j++) rmax = fmaxf(rmax, acc[i][j]);
            #pragma unroll
            for (int s = 8; s > 0; s >>= 1)
                rmax = fmaxf(rmax, __shfl_xor_sync(0xffffffffu, rmax, s, 16));

            float mnew  = fmaxf(m_i[i], rmax);
            float scale = __expf(m_i[i] - mnew);
            float p[8], rsum = 0.0f;
            #pragma unroll
            for (int j = 0; j < 8; j++) { p[j] = __expf(acc[i][j] - mnew); rsum += p[j]; }
            #pragma unroll
            for (int s = 8; s > 0; s >>= 1)
                rsum += __shfl_xor_sync(0xffffffffu, rsum, s, 16);

            l_i[i] = l_i[i] * scale + rsum;
            m_i[i] = mnew;
            #pragma unroll
            for (int n = 0; n < 4; n++) O[i][n] *= scale;

            *(float4*)&KP[(ty * 8 + i) * 128 + tx * 8]     = make_float4(p[0], p[1], p[2], p[3]);
            *(float4*)&KP[(ty * 8 + i) * 128 + tx * 8 + 4] = make_float4(p[4], p[5], p[6], p[7]);
        }
        __syncthreads();

        #pragma unroll 1
        for (int j4 = 0; j4 < 128; j4 += 4) {
            float pf[8][4];
            #pragma unroll
            for (int i = 0; i < 8; i++) {
                float4 p4 = *(const float4*)&KP[(ty * 8 + i) * 128 + j4];
                pf[i][0] = p4.x; pf[i][1] = p4.y; pf[i][2] = p4.z; pf[i][3] = p4.w;
            }
            float vf[4][4];
            #pragma unroll
            for (int m = 0; m < 4; m++) {
                float4 v4 = *(const float4*)&Vs[(j4 + m) * 64 + tx * 4];
                vf[m][0] = v4.x; vf[m][1] = v4.y; vf[m][2] = v4.z; vf[m][3] = v4.w;
            }
            #pragma unroll
            for (int i = 0; i < 8; i++)
                #pragma unroll
                for (int m = 0; m < 4; m++)
                    #pragma unroll
                    for (int n = 0; n < 4; n++)
                        O[i][n] += pf[i][m] * vf[m][n];
        }
    }

    #pragma unroll
    for (int i = 0; i < 8; i++) {
        float inv = 1.0f / l_i[i];
        size_t orow = (size_t)(b * TT + t0 + ty * 8 + i) * DD + h * HD + tx * 4;
        *(float4*)(outp + orow) = make_float4(O[i][0] * inv, O[i][1] * inv,
                                              O[i][2] * inv, O[i][3] * inv);
    }
}

// ---------------------------------------------------------------------------
// kernel_launch
// ---------------------------------------------------------------------------
extern "C" void kernel_launch(void* const* d_in, const int* in_sizes, int n_in,
                              void* d_out, int out_size) {
    const float* x      = (const float*)d_in[0];   // [4,2048,1024]
    const float* w_qkv  = (const float*)d_in[1];   // [1024,3072]
    const float* w_proj = (const float*)d_in[2];   // [1024,1024]
    float* out = (float*)d_out;                    // [4,2048,1024]

    float *qkv_p, *att_p;
    __nv_bfloat16 *ah, *al, *bh, *bl;
    cudaGetSymbolAddress((void**)&qkv_p, g_qkv);
    cudaGetSymbolAddress((void**)&att_p, g_att);
    cudaGetSymbolAddress((void**)&ah, g_ah);
    cudaGetSymbolAddress((void**)&al, g_al);
    cudaGetSymbolAddress((void**)&bh, g_bh);
    cudaGetSymbolAddress((void**)&bl, g_bl);

    const int gemm_smem = 2 * STG * 2;             // 81920 bytes
    cudaFuncSetAttribute(attn_kernel, cudaFuncAttributeMaxDynamicSharedMemorySize, 131072);
    cudaFuncSetAttribute(gemm_mma, cudaFuncAttributeMaxDynamicSharedMemorySize, gemm_smem);

    const int n_act = BT * DD;                     // 8388608

    // 1) Split x and w_qkv^T to bf16 hi/lo
    split_kernel<<<n_act / 1024, 256>>>(x, ah, al, n_act);
    transpose_split<<<dim3(D3 / 32, DD / 32), 256>>>(w_qkv, bh, bl, DD, D3);
    // 2) QKV projection on tensor cores: [8192,1024] @ [1024,3072]
    gemm_mma<<<dim3(D3 / 128, BT / 128), 256, gemm_smem>>>(ah, al, bh, bl, qkv_p, D3, DD);
    // 3) Attention (fp32)
    attn_kernel<<<dim3(TT / 128, HH, BB), 256, 131072>>>(qkv_p, att_p);
    // 4) Split att and w_proj^T
    split_kernel<<<n_act / 1024, 256>>>(att_p, ah, al, n_act);
    transpose_split<<<dim3(DD / 32, DD / 32), 256>>>(w_proj, bh, bl, DD, DD);
    // 5) Output projection on tensor cores: [8192,1024] @ [1024,1024]
    gemm_mma<<<dim3(DD / 128, BT / 128), 256, gemm_smem>>>(ah, al, bh, bl, out, DD, DD);
}

// round 7
// speedup vs baseline: 2.3101x; 1.6735x over previous
#include <cuda_runtime.h>
#include <cuda_bf16.h>
#include <math.h>
#include <stdint.h>

// Problem constants
#define BB   4
#define TT   2048
#define DD   1024
#define HH   16
#define HD   64
#define BT   (BB * TT)        // 8192
#define D3   (3 * DD)         // 3072

// Scratch (allocation-free rule: __device__ globals)
__device__ __nv_bfloat16 g_qh[BT * D3];     // qkv hi [8192][3072]
__device__ __nv_bfloat16 g_ql[BT * D3];     // qkv lo
__device__ __nv_bfloat16 g_ah[BT * DD];     // activation hi (x-split, then attn out)
__device__ __nv_bfloat16 g_al[BT * DD];     // activation lo
__device__ __nv_bfloat16 g_bh[DD * D3];     // weight^T hi
__device__ __nv_bfloat16 g_bl[DD * D3];     // weight^T lo

__device__ __forceinline__ uint32_t smem_u32(const void* p) {
    uint32_t a;
    asm("{ .reg .u64 t; cvta.to.shared.u64 t, %1; cvt.u32.u64 %0, t; }" : "=r"(a) : "l"(p));
    return a;
}

#define CP_ASYNC16(saddr, gptr) \
    asm volatile("cp.async.cg.shared.global [%0], [%1], 16;" :: "r"(saddr), "l"(gptr) : "memory")
#define CP_COMMIT() asm volatile("cp.async.commit_group;" ::: "memory")
#define CP_WAIT1()  asm volatile("cp.async.wait_group 1;" ::: "memory")
#define CP_WAIT0()  asm volatile("cp.async.wait_group 0;" ::: "memory")

__device__ __forceinline__ void mma16816(float* c, const uint32_t* a, const uint32_t* b) {
    asm volatile(
        "mma.sync.aligned.m16n8k16.row.col.f32.bf16.bf16.f32 "
        "{%0,%1,%2,%3}, {%4,%5,%6,%7}, {%8,%9}, {%0,%1,%2,%3};"
        : "+f"(c[0]), "+f"(c[1]), "+f"(c[2]), "+f"(c[3])
        : "r"(a[0]), "r"(a[1]), "r"(a[2]), "r"(a[3]), "r"(b[0]), "r"(b[1]));
}

// pack two floats as bf16x2 (lo in low half) + hi/lo split helpers
__device__ __forceinline__ uint32_t packbf(float a, float b) {
    __nv_bfloat162 t(__float2bfloat16(a), __float2bfloat16(b));
    return *(uint32_t*)&t;
}
__device__ __forceinline__ void split2(float a, float b, uint32_t& h, uint32_t& l) {
    __nv_bfloat16 ha = __float2bfloat16(a), hb = __float2bfloat16(b);
    __nv_bfloat16 la = __float2bfloat16(a - __bfloat162float(ha));
    __nv_bfloat16 lb = __float2bfloat16(b - __bfloat162float(hb));
    __nv_bfloat162 H(ha, hb), L(la, lb);
    h = *(uint32_t*)&H; l = *(uint32_t*)&L;
}

// ---------------------------------------------------------------------------
// fp32 -> (hi, lo) bf16 split, elementwise.
// ---------------------------------------------------------------------------
__global__ __launch_bounds__(256)
void split_kernel(const float* __restrict__ in, __nv_bfloat16* __restrict__ hi,
                  __nv_bfloat16* __restrict__ lo, int n) {
    int i = (blockIdx.x * 256 + threadIdx.x) * 4;
    if (i >= n) return;
    float4 v = *(const float4*)(in + i);
    uint32_t h0, l0, h1, l1;
    split2(v.x, v.y, h0, l0);
    split2(v.z, v.w, h1, l1);
    uint32_t* hp = (uint32_t*)(hi + i);
    uint32_t* lp = (uint32_t*)(lo + i);
    hp[0] = h0; hp[1] = h1; lp[0] = l0; lp[1] = l1;
}

// ---------------------------------------------------------------------------
// W [K,N] fp32 row-major -> Wt hi/lo [N,K] bf16 row-major (transpose + split)
// ---------------------------------------------------------------------------
__global__ __launch_bounds__(256)
void transpose_split(const float* __restrict__ W, __nv_bfloat16* __restrict__ Th,
                     __nv_bfloat16* __restrict__ Tl, int K, int N) {
    __shared__ float t[32][33];
    const int k0 = blockIdx.y * 32, n0 = blockIdx.x * 32;
    const int tx = threadIdx.x & 31, ty = threadIdx.x >> 5;
    #pragma unroll
    for (int i = 0; i < 32; i += 8)
        t[ty + i][tx] = W[(size_t)(k0 + ty + i) * N + n0 + tx];
    __syncthreads();
    #pragma unroll
    for (int i = 0; i < 32; i += 8) {
        float v = t[tx][ty + i];
        __nv_bfloat16 h = __float2bfloat16(v);
        size_t o = (size_t)(n0 + ty + i) * K + k0 + tx;
        Th[o] = h;
        Tl[o] = __float2bfloat16(v - __bfloat162float(h));
    }
}

// ---------------------------------------------------------------------------
// mma.sync bf16 split-GEMM (fp32-equivalent). SPLIT_OUT: write hi/lo bf16.
// ---------------------------------------------------------------------------
#define TS   (128 * 40)
#define STG  (4 * TS)

template <bool SPLIT_OUT>
__global__ __launch_bounds__(256)
void gemm_mma(const __nv_bfloat16* __restrict__ Ah, const __nv_bfloat16* __restrict__ Al,
              const __nv_bfloat16* __restrict__ Bh, const __nv_bfloat16* __restrict__ Bl,
              float* __restrict__ C, __nv_bfloat16* __restrict__ Ch,
              __nv_bfloat16* __restrict__ Cl, int N, int K) {
    extern __shared__ __align__(16) __nv_bfloat16 sm[];
    const uint32_t sb = smem_u32(sm);

    const int tid  = threadIdx.x;
    const int wid  = tid >> 5;
    const int lane = tid & 31;
    const int g    = lane >> 2;
    const int tg   = lane & 3;
    const int wm   = (wid >> 1) * 32;
    const int wn   = (wid & 1) * 64;
    const int m0   = blockIdx.y * 128;
    const int n0   = blockIdx.x * 128;

    float acc[2][8][4];
    #pragma unroll
    for (int i = 0; i < 2; i++)
        #pragma unroll
        for (int j = 0; j < 8; j++)
            #pragma unroll
            for (int c = 0; c < 4; c++) acc[i][j][c] = 0.0f;

    const int KT = K >> 5;

    auto issue = [&](int stage, int kt) {
        const int k0 = kt * 32;
        uint32_t sbase = sb + stage * STG * 2;
        #pragma unroll
        for (int h = 0; h < 2; h++) {
            int c   = tid + h * 256;
            int row = c >> 2;
            int cc  = c & 3;
            size_t ga = (size_t)(m0 + row) * K + k0 + cc * 8;
            size_t gb = (size_t)(n0 + row) * K + k0 + cc * 8;
            uint32_t so = (uint32_t)(row * 80 + cc * 16);
            CP_ASYNC16(sbase + so,          Ah + ga);
            CP_ASYNC16(sbase + TS * 2 + so, Al + ga);
            CP_ASYNC16(sbase + TS * 4 + so, Bh + gb);
            CP_ASYNC16(sbase + TS * 6 + so, Bl + gb);
        }
        CP_COMMIT();
    };

    issue(0, 0);

    for (int kt = 0; kt < KT; kt++) {
        const int stage = kt & 1;
        if (kt + 1 < KT) { issue(stage ^ 1, kt + 1); CP_WAIT1(); }
        else             { CP_WAIT0(); }
        __syncthreads();

        const __nv_bfloat16* sAh = sm + stage * STG;
        const __nv_bfloat16* sAl = sAh + TS;
        const __nv_bfloat16* sBh = sAh + 2 * TS;
        const __nv_bfloat16* sBl = sAh + 3 * TS;

        #pragma unroll
        for (int ks = 0; ks < 32; ks += 16) {
            uint32_t ah[2][4], al[2][4], bh[8][2], bl[8][2];
            #pragma unroll
            for (int i = 0; i < 2; i++) {
                int r = wm + i * 16 + g;
                int cA = ks + tg * 2;
                ah[i][0] = *(const uint32_t*)&sAh[r * 40 + cA];
                ah[i][1] = *(const uint32_t*)&sAh[(r + 8) * 40 + cA];
                ah[i][2] = *(const uint32_t*)&sAh[r * 40 + cA + 8];
                ah[i][3] = *(const uint32_t*)&sAh[(r + 8) * 40 + cA + 8];
                al[i][0] = *(const uint32_t*)&sAl[r * 40 + cA];
                al[i][1] = *(const uint32_t*)&sAl[(r + 8) * 40 + cA];
                al[i][2] = *(const uint32_t*)&sAl[r * 40 + cA + 8];
                al[i][3] = *(const uint32_t*)&sAl[(r + 8) * 40 + cA + 8];
            }
            #pragma unroll
            for (int j = 0; j < 8; j++) {
                int rn = wn + j * 8 + g;
                int cB = ks + tg * 2;
                bh[j][0] = *(const uint32_t*)&sBh[rn * 40 + cB];
                bh[j][1] = *(const uint32_t*)&sBh[rn * 40 + cB + 8];
                bl[j][0] = *(const uint32_t*)&sBl[rn * 40 + cB];
                bl[j][1] = *(const uint32_t*)&sBl[rn * 40 + cB + 8];
            }
            #pragma unroll
            for (int i = 0; i < 2; i++)
                #pragma unroll
                for (int j = 0; j < 8; j++) {
                    mma16816(acc[i][j], ah[i], bh[j]);
                    mma16816(acc[i][j], ah[i], bl[j]);
                    mma16816(acc[i][j], al[i], bh[j]);
                }
        }
        __syncthreads();
    }

    #pragma unroll
    for (int i = 0; i < 2; i++) {
        int r0 = m0 + wm + i * 16 + g;
        #pragma unroll
        for (int j = 0; j < 8; j++) {
            int cc = n0 + wn + j * 8 + tg * 2;
            if constexpr (SPLIT_OUT) {
                uint32_t h01, l01, h23, l23;
                split2(acc[i][j][0], acc[i][j][1], h01, l01);
                split2(acc[i][j][2], acc[i][j][3], h23, l23);
                *(uint32_t*)(Ch + (size_t)r0 * N + cc)       = h01;
                *(uint32_t*)(Cl + (size_t)r0 * N + cc)       = l01;
                *(uint32_t*)(Ch + (size_t)(r0 + 8) * N + cc) = h23;
                *(uint32_t*)(Cl + (size_t)(r0 + 8) * N + cc) = l23;
            } else {
                *(float2*)(C + (size_t)r0 * N + cc)       = make_float2(acc[i][j][0], acc[i][j][1]);
                *(float2*)(C + (size_t)(r0 + 8) * N + cc) = make_float2(acc[i][j][2], acc[i][j][3]);
            }
        }
    }
}

// ---------------------------------------------------------------------------
// Flash attention on mma.sync bf16 (split 3-term everywhere).
// grid (T/128, H, B), 256 threads (8 warps). Warp w owns q-rows [w*16, w*16+16)
// x full 128 kv cols -> softmax reduces intra-warp only; P stays in registers.
// smem (bytes): Qh 0 | Ql 18432 | K stage0 h/l 36864/55296 | stage1 73728/92160
//               Vt h 110592 | Vt l 128000 | total 145408
// ---------------------------------------------------------------------------
#define QSTR 72
#define VSTR 136
#define SM_QH 0
#define SM_QL 18432
#define SM_K0 36864
#define SM_VH 110592
#define SM_VL 128000
#define ATTN_SMEM 145408

__global__ __launch_bounds__(256, 1)
void attn_mma(const __nv_bfloat16* __restrict__ qh, const __nv_bfloat16* __restrict__ ql,
              __nv_bfloat16* __restrict__ oh, __nv_bfloat16* __restrict__ ol) {
    extern __shared__ __align__(16) char smc[];
    __nv_bfloat16* smb = (__nv_bfloat16*)smc;
    const uint32_t sb = smem_u32(smc);

    const int tid  = threadIdx.x;
    const int wid  = tid >> 5;
    const int lane = tid & 31;
    const int g    = lane >> 2;
    const int tg   = lane & 3;
    const int wq   = wid * 16;               // warp's q-row base in tile
    const int qb   = blockIdx.x;
    const int h    = blockIdx.y;
    const int b    = blockIdx.z;
    const int t0   = qb * 128;

    // loader mapping: row = tid>>1 (0..127), cbase = (tid&1)*32
    const int lrow  = tid >> 1;
    const int cbase = (tid & 1) * 32;

    const size_t qgrow = ((size_t)(b * TT + t0) + lrow) * D3 + h * HD + cbase;

    // Prologue: Q + K(0) via cp.async, V(0) via LDG
    #pragma unroll
    for (int i = 0; i < 4; i++) {
        uint32_t so = (uint32_t)(lrow * (QSTR * 2) + (cbase + i * 8) * 2);
        CP_ASYNC16(sb + SM_QH + so, qh + qgrow + i * 8);
        CP_ASYNC16(sb + SM_QL + so, ql + qgrow + i * 8);
    }
    {
        const size_t kgrow = ((size_t)(b * TT) + lrow) * D3 + DD + h * HD + cbase;
        #pragma unroll
        for (int i = 0; i < 4; i++) {
            uint32_t so = (uint32_t)(lrow * (QSTR * 2) + (cbase + i * 8) * 2);
            CP_ASYNC16(sb + SM_K0 + so,         qh + kgrow + i * 8);
            CP_ASYNC16(sb + SM_K0 + 18432 + so, ql + kgrow + i * 8);
        }
    }
    CP_COMMIT();

    uint4 vrh[4], vrl[4];
    {
        const size_t vgrow = ((size_t)(b * TT) + lrow) * D3 + 2 * DD + h * HD + cbase;
        #pragma unroll
        for (int i = 0; i < 4; i++) {
            vrh[i] = *(const uint4*)(qh + vgrow + i * 8);
            vrl[i] = *(const uint4*)(ql + vgrow + i * 8);
        }
    }

    CP_WAIT0();
    __syncthreads();

    // Q fragments (stay in registers for whole kernel)
    uint32_t aQh[4][4], aQl[4][4];
    {
        const __nv_bfloat16* Qh = smb;           // SM_QH
        const __nv_bfloat16* Ql = smb + 9216;    // SM_QL/2
        int r = wq + g;
        #pragma unroll
        for (int ks = 0; ks < 4; ks++) {
            int cA = ks * 16 + tg * 2;
            aQh[ks][0] = *(const uint32_t*)&Qh[r * QSTR + cA];
            aQh[ks][1] = *(const uint32_t*)&Qh[(r + 8) * QSTR + cA];
            aQh[ks][2] = *(const uint32_t*)&Qh[r * QSTR + cA + 8];
            aQh[ks][3] = *(const uint32_t*)&Qh[(r + 8) * QSTR + cA + 8];
            aQl[ks][0] = *(const uint32_t*)&Ql[r * QSTR + cA];
            aQl[ks][1] = *(const uint32_t*)&Ql[(r + 8) * QSTR + cA];
            aQl[ks][2] = *(const uint32_t*)&Ql[r * QSTR + cA + 8];
            aQl[ks][3] = *(const uint32_t*)&Ql[(r + 8) * QSTR + cA + 8];
        }
    }

    // Scatter V(0) into transposed smem [hd][kv]
    {
        __nv_bfloat16* Vth = (__nv_bfloat16*)(smc + SM_VH);
        __nv_bfloat16* Vtl = (__nv_bfloat16*)(smc + SM_VL);
        #pragma unroll
        for (int i = 0; i < 4; i++) {
            const __nv_bfloat16* eh = (const __nv_bfloat16*)&vrh[i];
            const __nv_bfloat16* el = (const __nv_bfloat16*)&vrl[i];
            #pragma unroll
            for (int e = 0; e < 8; e++) {
                int c = cbase + i * 8 + e;
                Vth[c * VSTR + lrow] = eh[e];
                Vtl[c * VSTR + lrow] = el[e];
            }
        }
    }
    __syncthreads();

    float O[8][4];
    #pragma unroll
    for (int j = 0; j < 8; j++)
        #pragma unroll
        for (int c = 0; c < 4; c++) O[j][c] = 0.0f;
    float m0v = -1e30f, m1v = -1e30f, l0v = 0.0f, l1v = 0.0f;

    const int NT = TT / 128;
    for (int kv = 0; kv < NT; kv++) {
        const int stage = kv & 1;
        // prefetch next K via cp.async, next V into registers
        if (kv + 1 < NT) {
            const size_t base = ((size_t)(b * TT + (kv + 1) * 128) + lrow) * D3 + h * HD + cbase;
            const size_t kgrow = base + DD;
            uint32_t kdst = sb + SM_K0 + (stage ^ 1) * 36864;
            #pragma unroll
            for (int i = 0; i < 4; i++) {
                uint32_t so = (uint32_t)(lrow * (QSTR * 2) + (cbase + i * 8) * 2);
                CP_ASYNC16(kdst + so,         qh + kgrow + i * 8);
                CP_ASYNC16(kdst + 18432 + so, ql + kgrow + i * 8);
            }
            CP_COMMIT();
            const size_t vgrow = base + 2 * DD;
            #pragma unroll
            for (int i = 0; i < 4; i++) {
                vrh[i] = *(const uint4*)(qh + vgrow + i * 8);
                vrl[i] = *(const uint4*)(ql + vgrow + i * 8);
            }
        }

        // ---- S = Q K^T ----
        float c[16][4];
        #pragma unroll
        for (int j = 0; j < 16; j++)
            #pragma unroll
            for (int x = 0; x < 4; x++) c[j][x] = 0.0f;

        const __nv_bfloat16* Kh = (const __nv_bfloat16*)(smc + SM_K0 + stage * 36864);
        const __nv_bfloat16* Kl = Kh + 9216;
        #pragma unroll
        for (int ks = 0; ks < 4; ks++) {
            int cB = ks * 16 + tg * 2;
            #pragma unroll
            for (int j = 0; j < 16; j++) {
                int rn = j * 8 + g;
                uint32_t bh[2], bl[2];
                bh[0] = *(const uint32_t*)&Kh[rn * QSTR + cB];
                bh[1] = *(const uint32_t*)&Kh[rn * QSTR + cB + 8];
                bl[0] = *(const uint32_t*)&Kl[rn * QSTR + cB];
                bl[1] = *(const uint32_t*)&Kl[rn * QSTR + cB + 8];
                mma16816(c[j], aQh[ks], bh);
                mma16816(c[j], aQh[ks], bl);
                mma16816(c[j], aQl[ks], bh);
            }
        }

        // ---- online softmax (rows g and g+8; cols within warp) ----
        float mx0 = c[0][0], mx1 = c[0][2];
        #pragma unroll
        for (int j = 0; j < 16; j++) {
            mx0 = fmaxf(mx0, fmaxf(c[j][0], c[j][1]));
            mx1 = fmaxf(mx1, fmaxf(c[j][2], c[j][3]));
        }
        mx0 = fmaxf(mx0, __shfl_xor_sync(0xffffffffu, mx0, 1));
        mx0 = fmaxf(mx0, __shfl_xor_sync(0xffffffffu, mx0, 2));
        mx1 = fmaxf(mx1, __shfl_xor_sync(0xffffffffu, mx1, 1));
        mx1 = fmaxf(mx1, __shfl_xor_sync(0xffffffffu, mx1, 2));

        float mn0 = fmaxf(m0v, mx0), mn1 = fmaxf(m1v, mx1);
        float sc0 = __expf(m0v - mn0), sc1 = __expf(m1v - mn1);
        float sum0 = 0.0f, sum1 = 0.0f;
        #pragma unroll
        for (int j = 0; j < 16; j++) {
            c[j][0] = __expf(c[j][0] - mn0); sum0 += c[j][0];
            c[j][1] = __expf(c[j][1] - mn0); sum0 += c[j][1];
            c[j][2] = __expf(c[j][2] - mn1); sum1 += c[j][2];
            c[j][3] = __expf(c[j][3] - mn1); sum1 += c[j][3];
        }
        sum0 += __shfl_xor_sync(0xffffffffu, sum0, 1);
        sum0 += __shfl_xor_sync(0xffffffffu, sum0, 2);
        sum1 += __shfl_xor_sync(0xffffffffu, sum1, 1);
        sum1 += __shfl_xor_sync(0xffffffffu, sum1, 2);
        l0v = l0v * sc0 + sum0;  m0v = mn0;
        l1v = l1v * sc1 + sum1;  m1v = mn1;
        #pragma unroll
        for (int j = 0; j < 8; j++) {
            O[j][0] *= sc0; O[j][1] *= sc0; O[j][2] *= sc1; O[j][3] *= sc1;
        }

        // ---- O += P V ----
        const __nv_bfloat16* Vth = (const __nv_bfloat16*)(smc + SM_VH);
        const __nv_bfloat16* Vtl = (const __nv_bfloat16*)(smc + SM_VL);
        #pragma unroll
        for (int kk = 0; kk < 8; kk++) {
            uint32_t ph[4], pl[4];
            split2(c[2 * kk][0],     c[2 * kk][1],     ph[0], pl[0]);
            split2(c[2 * kk][2],     c[2 * kk][3],     ph[1], pl[1]);
            split2(c[2 * kk + 1][0], c[2 * kk + 1][1], ph[2], pl[2]);
            split2(c[2 * kk + 1][2], c[2 * kk + 1][3], ph[3], pl[3]);
            int cB = kk * 16 + tg * 2;
            #pragma unroll
            for (int jn = 0; jn < 8; jn++) {
                int rn = jn * 8 + g;
                uint32_t bh[2], bl[2];
                bh[0] = *(const uint32_t*)&Vth[rn * VSTR + cB];
                bh[1] = *(const uint32_t*)&Vth[rn * VSTR + cB + 8];
                bl[0] = *(const uint32_t*)&Vtl[rn * VSTR + cB];
                bl[1] = *(const uint32_t*)&Vtl[rn * VSTR + cB + 8];
                mma16816(O[jn], ph, bh);
                mma16816(O[jn], ph, bl);
                mma16816(O[jn], pl, bh);
            }
        }

        __syncthreads();     // all warps done reading Vt
        if (kv + 1 < NT) {
            __nv_bfloat16* Vth2 = (__nv_bfloat16*)(smc + SM_VH);
            __nv_bfloat16* Vtl2 = (__nv_bfloat16*)(smc + SM_VL);
            #pragma unroll
            for (int i = 0; i < 4; i++) {
                const __nv_bfloat16* eh = (const __nv_bfloat16*)&vrh[i];
                const __nv_bfloat16* el = (const __nv_bfloat16*)&vrl[i];
                #pragma unroll
                for (int e = 0; e < 8; e++) {
                    int cc = cbase + i * 8 + e;
                    Vth2[cc * VSTR + lrow] = eh[e];
                    Vtl2[cc * VSTR + lrow] = el[e];
                }
            }
            CP_WAIT0();
        }
        __syncthreads();
    }

    // Epilogue: normalize, split, write bf16 hi/lo to proj-A buffers [8192][1024]
    float inv0 = 1.0f / l0v, inv1 = 1.0f / l1v;
    size_t r0 = (size_t)(b * TT + t0 + wq + g);
    size_t col = h * HD + tg * 2;
    #pragma unroll
    for (int jn = 0; jn < 8; jn++) {
        uint32_t h01, l01, h23, l23;
        split2(O[jn][0] * inv0, O[jn][1] * inv0, h01, l01);
        split2(O[jn][2] * inv1, O[jn][3] * inv1, h23, l23);
        size_t o0 = r0 * DD + col + jn * 8;
        size_t o1 = (r0 + 8) * DD + col + jn * 8;
        *(uint32_t*)(oh + o0) = h01;
        *(uint32_t*)(ol + o0) = l01;
        *(uint32_t*)(oh + o1) = h23;
        *(uint32_t*)(ol + o1) = l23;
    }
}

// ---------------------------------------------------------------------------
// kernel_launch
// ---------------------------------------------------------------------------
extern "C" void kernel_launch(void* const* d_in, const int* in_sizes, int n_in,
                              void* d_out, int out_size) {
    const float* x      = (const float*)d_in[0];
    const float* w_qkv  = (const float*)d_in[1];
    const float* w_proj = (const float*)d_in[2];
    float* out = (float*)d_out;

    __nv_bfloat16 *qh, *ql, *ah, *al, *bh, *bl;
    cudaGetSymbolAddress((void**)&qh, g_qh);
    cudaGetSymbolAddress((void**)&ql, g_ql);
    cudaGetSymbolAddress((void**)&ah, g_ah);
    cudaGetSymbolAddress((void**)&al, g_al);
    cudaGetSymbolAddress((void**)&bh, g_bh);
    cudaGetSymbolAddress((void**)&bl, g_bl);

    const int gemm_smem = 2 * STG * 2;
    cudaFuncSetAttribute(gemm_mma<true>,  cudaFuncAttributeMaxDynamicSharedMemorySize, gemm_smem);
    cudaFuncSetAttribute(gemm_mma<false>, cudaFuncAttributeMaxDynamicSharedMemorySize, gemm_smem);
    cudaFuncSetAttribute(attn_mma, cudaFuncAttributeMaxDynamicSharedMemorySize, ATTN_SMEM);

    const int n_act = BT * DD;

    // 1) Split x; transpose+split w_qkv
    split_kernel<<<n_act / 1024, 256>>>(x, ah, al, n_act);
    transpose_split<<<dim3(D3 / 32, DD / 32), 256>>>(w_qkv, bh, bl, DD, D3);
    // 2) QKV projection -> split bf16 output
    gemm_mma<true><<<dim3(D3 / 128, BT / 128), 256, gemm_smem>>>(
        ah, al, bh, bl, nullptr, qh, ql, D3, DD);
    // 3) Attention (tensor-core, split) -> split bf16 output into ah/al
    attn_mma<<<dim3(TT / 128, HH, BB), 256, ATTN_SMEM>>>(qh, ql, ah, al);
    // 4) transpose+split w_proj; output projection -> fp32 out
    transpose_split<<<dim3(DD / 32, DD / 32), 256>>>(w_proj, bh, bl, DD, DD);
    gemm_mma<false><<<dim3(DD / 128, BT / 128), 256, gemm_smem>>>(
        ah, al, bh, bl, out, nullptr, nullptr, DD, DD);
}

// round 9
// speedup vs baseline: 2.6132x; 1.1312x over previous
#include <cuda_runtime.h>
#include <cuda_bf16.h>
#include <math.h>
#include <stdint.h>

// Problem constants
#define BB   4
#define TT   2048
#define DD   1024
#define HH   16
#define HD   64
#define BT   (BB * TT)        // 8192
#define D3   (3 * DD)         // 3072

// Scratch (allocation-free rule: __device__ globals)
__device__ __nv_bfloat16 g_qh[BT * D3];     // qkv hi [8192][3072]
__device__ __nv_bfloat16 g_ql[BT * D3];     // qkv lo
__device__ __nv_bfloat16 g_ah[BT * DD];     // activation hi (x-split, then attn out)
__device__ __nv_bfloat16 g_al[BT * DD];     // activation lo
__device__ __nv_bfloat16 g_bh[DD * D3];     // weight^T hi
__device__ __nv_bfloat16 g_bl[DD * D3];     // weight^T lo

__device__ __forceinline__ uint32_t smem_u32(const void* p) {
    uint32_t a;
    asm("{ .reg .u64 t; cvta.to.shared.u64 t, %1; cvt.u32.u64 %0, t; }" : "=r"(a) : "l"(p));
    return a;
}

#define CP_ASYNC16(saddr, gptr) \
    asm volatile("cp.async.cg.shared.global [%0], [%1], 16;" :: "r"(saddr), "l"(gptr) : "memory")
#define CP_COMMIT() asm volatile("cp.async.commit_group;" ::: "memory")
#define CP_WAIT1()  asm volatile("cp.async.wait_group 1;" ::: "memory")
#define CP_WAIT0()  asm volatile("cp.async.wait_group 0;" ::: "memory")

__device__ __forceinline__ void mma16816(float* c, const uint32_t* a, const uint32_t* b) {
    asm volatile(
        "mma.sync.aligned.m16n8k16.row.col.f32.bf16.bf16.f32 "
        "{%0,%1,%2,%3}, {%4,%5,%6,%7}, {%8,%9}, {%0,%1,%2,%3};"
        : "+f"(c[0]), "+f"(c[1]), "+f"(c[2]), "+f"(c[3])
        : "r"(a[0]), "r"(a[1]), "r"(a[2]), "r"(a[3]), "r"(b[0]), "r"(b[1]));
}

__device__ __forceinline__ void ldsm_x4(uint32_t* r, uint32_t addr) {
    asm volatile("ldmatrix.sync.aligned.m8n8.x4.shared.b16 {%0,%1,%2,%3}, [%4];"
                 : "=r"(r[0]), "=r"(r[1]), "=r"(r[2]), "=r"(r[3]) : "r"(addr));
}
__device__ __forceinline__ void ldsm_x4_t(uint32_t* r, uint32_t addr) {
    asm volatile("ldmatrix.sync.aligned.m8n8.x4.trans.shared.b16 {%0,%1,%2,%3}, [%4];"
                 : "=r"(r[0]), "=r"(r[1]), "=r"(r[2]), "=r"(r[3]) : "r"(addr));
}

__device__ __forceinline__ void split2(float a, float b, uint32_t& h, uint32_t& l) {
    __nv_bfloat16 ha = __float2bfloat16(a), hb = __float2bfloat16(b);
    __nv_bfloat16 la = __float2bfloat16(a - __bfloat162float(ha));
    __nv_bfloat16 lb = __float2bfloat16(b - __bfloat162float(hb));
    __nv_bfloat162 H(ha, hb), L(la, lb);
    h = *(uint32_t*)&H; l = *(uint32_t*)&L;
}

// ---------------------------------------------------------------------------
// fp32 -> (hi, lo) bf16 split, elementwise.
// ---------------------------------------------------------------------------
__global__ __launch_bounds__(256)
void split_kernel(const float* __restrict__ in, __nv_bfloat16* __restrict__ hi,
                  __nv_bfloat16* __restrict__ lo, int n) {
    int i = (blockIdx.x * 256 + threadIdx.x) * 4;
    if (i >= n) return;
    float4 v = *(const float4*)(in + i);
    uint32_t h0, l0, h1, l1;
    split2(v.x, v.y, h0, l0);
    split2(v.z, v.w, h1, l1);
    uint32_t* hp = (uint32_t*)(hi + i);
    uint32_t* lp = (uint32_t*)(lo + i);
    hp[0] = h0; hp[1] = h1; lp[0] = l0; lp[1] = l1;
}

// ---------------------------------------------------------------------------
// W [K,N] fp32 row-major -> Wt hi/lo [N,K] bf16 row-major (transpose + split)
// ---------------------------------------------------------------------------
__global__ __launch_bounds__(256)
void transpose_split(const float* __restrict__ W, __nv_bfloat16* __restrict__ Th,
                     __nv_bfloat16* __restrict__ Tl, int K, int N) {
    __shared__ float t[32][33];
    const int k0 = blockIdx.y * 32, n0 = blockIdx.x * 32;
    const int tx = threadIdx.x & 31, ty = threadIdx.x >> 5;
    #pragma unroll
    for (int i = 0; i < 32; i += 8)
        t[ty + i][tx] = W[(size_t)(k0 + ty + i) * N + n0 + tx];
    __syncthreads();
    #pragma unroll
    for (int i = 0; i < 32; i += 8) {
        float v = t[tx][ty + i];
        __nv_bfloat16 h = __float2bfloat16(v);
        size_t o = (size_t)(n0 + ty + i) * K + k0 + tx;
        Th[o] = h;
        Tl[o] = __float2bfloat16(v - __bfloat162float(h));
    }
}

// ---------------------------------------------------------------------------
// mma.sync bf16 split-GEMM, ldmatrix fragment loads.
// ---------------------------------------------------------------------------
#define TS   (128 * 40)
#define STG  (4 * TS)

template <bool SPLIT_OUT>
__global__ __launch_bounds__(256)
void gemm_mma(const __nv_bfloat16* __restrict__ Ah, const __nv_bfloat16* __restrict__ Al,
              const __nv_bfloat16* __restrict__ Bh, const __nv_bfloat16* __restrict__ Bl,
              float* __restrict__ C, __nv_bfloat16* __restrict__ Ch,
              __nv_bfloat16* __restrict__ Cl, int N, int K) {
    extern __shared__ __align__(16) __nv_bfloat16 sm[];
    const uint32_t sb = smem_u32(sm);

    const int tid  = threadIdx.x;
    const int wid  = tid >> 5;
    const int lane = tid & 31;
    const int g    = lane >> 2;
    const int tg   = lane & 3;
    const int wm   = (wid >> 1) * 32;
    const int wn   = (wid & 1) * 64;
    const int m0   = blockIdx.y * 128;
    const int n0   = blockIdx.x * 128;

    // ldmatrix lane-address components (elements)
    const int arow_l = ((lane >> 3) & 1) * 8 + (lane & 7);
    const int acol_l = (lane >> 4) * 8;
    const int brow_l = ((lane >> 4) & 1) * 8 + (lane & 7);
    const int bcol_l = ((lane >> 3) & 1) * 8;

    float acc[2][8][4];
    #pragma unroll
    for (int i = 0; i < 2; i++)
        #pragma unroll
        for (int j = 0; j < 8; j++)
            #pragma unroll
            for (int c = 0; c < 4; c++) acc[i][j][c] = 0.0f;

    const int KT = K >> 5;

    auto issue = [&](int stage, int kt) {
        const int k0 = kt * 32;
        uint32_t sbase = sb + stage * STG * 2;
        #pragma unroll
        for (int h = 0; h < 2; h++) {
            int c   = tid + h * 256;
            int row = c >> 2;
            int cc  = c & 3;
            size_t ga = (size_t)(m0 + row) * K + k0 + cc * 8;
            size_t gb = (size_t)(n0 + row) * K + k0 + cc * 8;
            uint32_t so = (uint32_t)(row * 80 + cc * 16);
            CP_ASYNC16(sbase + so,          Ah + ga);
            CP_ASYNC16(sbase + TS * 2 + so, Al + ga);
            CP_ASYNC16(sbase + TS * 4 + so, Bh + gb);
            CP_ASYNC16(sbase + TS * 6 + so, Bl + gb);
        }
        CP_COMMIT();
    };

    issue(0, 0);

    for (int kt = 0; kt < KT; kt++) {
        const int stage = kt & 1;
        if (kt + 1 < KT) { issue(stage ^ 1, kt + 1); CP_WAIT1(); }
        else             { CP_WAIT0(); }
        __syncthreads();

        const uint32_t sAh = sb + stage * STG * 2;
        const uint32_t sAl = sAh + TS * 2;
        const uint32_t sBh = sAh + TS * 4;
        const uint32_t sBl = sAh + TS * 6;

        #pragma unroll
        for (int ks = 0; ks < 32; ks += 16) {
            uint32_t ah[2][4], al[2][4], bh[4][4], bl[4][4];
            #pragma unroll
            for (int i = 0; i < 2; i++) {
                uint32_t off = (uint32_t)((wm + i * 16 + arow_l) * 40 + ks + acol_l) * 2;
                ldsm_x4(ah[i], sAh + off);
                ldsm_x4(al[i], sAl + off);
            }
            #pragma unroll
            for (int jp = 0; jp < 4; jp++) {
                uint32_t off = (uint32_t)((wn + jp * 16 + brow_l) * 40 + ks + bcol_l) * 2;
                ldsm_x4(bh[jp], sBh + off);
                ldsm_x4(bl[jp], sBl + off);
            }
            #pragma unroll
            for (int i = 0; i < 2; i++)
                #pragma unroll
                for (int jp = 0; jp < 4; jp++) {
                    mma16816(acc[i][2 * jp],     ah[i], &bh[jp][0]);
                    mma16816(acc[i][2 * jp],     ah[i], &bl[jp][0]);
                    mma16816(acc[i][2 * jp],     al[i], &bh[jp][0]);
                    mma16816(acc[i][2 * jp + 1], ah[i], &bh[jp][2]);
                    mma16816(acc[i][2 * jp + 1], ah[i], &bl[jp][2]);
                    mma16816(acc[i][2 * jp + 1], al[i], &bh[jp][2]);
                }
        }
        __syncthreads();
    }

    #pragma unroll
    for (int i = 0; i < 2; i++) {
        int r0 = m0 + wm + i * 16 + g;
        #pragma unroll
        for (int j = 0; j < 8; j++) {
            int cc = n0 + wn + j * 8 + tg * 2;
            if constexpr (SPLIT_OUT) {
                uint32_t h01, l01, h23, l23;
                split2(acc[i][j][0], acc[i][j][1], h01, l01);
                split2(acc[i][j][2], acc[i][j][3], h23, l23);
                *(uint32_t*)(Ch + (size_t)r0 * N + cc)       = h01;
                *(uint32_t*)(Cl + (size_t)r0 * N + cc)       = l01;
                *(uint32_t*)(Ch + (size_t)(r0 + 8) * N + cc) = h23;
                *(uint32_t*)(Cl + (size_t)(r0 + 8) * N + cc) = l23;
            } else {
                *(float2*)(C + (size_t)r0 * N + cc)       = make_float2(acc[i][j][0], acc[i][j][1]);
                *(float2*)(C + (size_t)(r0 + 8) * N + cc) = make_float2(acc[i][j][2], acc[i][j][3]);
            }
        }
    }
}

// ---------------------------------------------------------------------------
// Flash attention on mma.sync bf16 + ldmatrix fragments.
// K and V both natural [kv][hd] layout, cp.async double-buffered.
// V fragments via ldmatrix.trans (HW transpose, no scatter).
// smem (bytes): Qh 0 | Ql 18432 | stage s at 36864+s*73728:
//   Kh +0 | Kl +18432 | Vh +36864 | Vl +55296.  Total 184320.
// ---------------------------------------------------------------------------
#define ASTR 72
#define SM_ST0 36864
#define STAGE_B 73728
#define ATTN_SMEM 184320

__global__ __launch_bounds__(256, 1)
void attn_mma(const __nv_bfloat16* __restrict__ qh, const __nv_bfloat16* __restrict__ ql,
              __nv_bfloat16* __restrict__ oh, __nv_bfloat16* __restrict__ ol) {
    extern __shared__ __align__(16) char smc[];
    const uint32_t sb = smem_u32(smc);

    const int tid  = threadIdx.x;
    const int wid  = tid >> 5;
    const int lane = tid & 31;
    const int g    = lane >> 2;
    const int tg   = lane & 3;
    const int wq   = wid * 16;
    const int qb   = blockIdx.x;
    const int h    = blockIdx.y;
    const int b    = blockIdx.z;
    const int t0   = qb * 128;

    // loader mapping
    const int lrow  = tid >> 1;
    const int cbase = (tid & 1) * 32;

    // ldmatrix lane-address components
    const int arow_l = ((lane >> 3) & 1) * 8 + (lane & 7);   // A-frag row
    const int acol_l = (lane >> 4) * 8;                      // A-frag col
    const int brow_l = ((lane >> 4) & 1) * 8 + (lane & 7);   // B-frag (K) row
    const int bcol_l = ((lane >> 3) & 1) * 8;                // B-frag (K) col
    const int vrow_l = ((lane >> 3) & 1) * 8 + (lane & 7);   // V.trans source row (kv)
    const int vcol_l = ((lane >> 4) & 1) * 8;                // V.trans source col (hd)

    // Prologue: Q + K(0) + V(0) via cp.async (one group)
    {
        const size_t qgrow = ((size_t)(b * TT + t0) + lrow) * D3 + h * HD + cbase;
        const size_t base0 = ((size_t)(b * TT) + lrow) * D3 + h * HD + cbase;
        #pragma unroll
        for (int i = 0; i < 4; i++) {
            uint32_t so = (uint32_t)(lrow * (ASTR * 2) + (cbase + i * 8) * 2);
            CP_ASYNC16(sb + so,         qh + qgrow + i * 8);
            CP_ASYNC16(sb + 18432 + so, ql + qgrow + i * 8);
            CP_ASYNC16(sb + SM_ST0 + so,         qh + base0 + DD + i * 8);
            CP_ASYNC16(sb + SM_ST0 + 18432 + so, ql + base0 + DD + i * 8);
            CP_ASYNC16(sb + SM_ST0 + 36864 + so, qh + base0 + 2 * DD + i * 8);
            CP_ASYNC16(sb + SM_ST0 + 55296 + so, ql + base0 + 2 * DD + i * 8);
        }
        CP_COMMIT();
    }
    CP_WAIT0();
    __syncthreads();

    // Q fragments (persistent in registers)
    uint32_t aQh[4][4], aQl[4][4];
    #pragma unroll
    for (int ks = 0; ks < 4; ks++) {
        uint32_t off = (uint32_t)((wq + arow_l) * ASTR + ks * 16 + acol_l) * 2;
        ldsm_x4(aQh[ks], sb + off);
        ldsm_x4(aQl[ks], sb + 18432 + off);
    }

    float O[8][4];
    #pragma unroll
    for (int j = 0; j < 8; j++)
        #pragma unroll
        for (int c = 0; c < 4; c++) O[j][c] = 0.0f;
    float m0v = -1e30f, m1v = -1e30f, l0v = 0.0f, l1v = 0.0f;

    const int NT = TT / 128;
    for (int kv = 0; kv < NT; kv++) {
        const int stage = kv & 1;
        if (kv > 0) { CP_WAIT0(); __syncthreads(); }

        // prefetch next stage (after sync: no warp still reads stage^1)
        if (kv + 1 < NT) {
            const size_t base = ((size_t)(b * TT + (kv + 1) * 128) + lrow) * D3 + h * HD + cbase;
            uint32_t dst = sb + SM_ST0 + (stage ^ 1) * STAGE_B;
            #pragma unroll
            for (int i = 0; i < 4; i++) {
                uint32_t so = (uint32_t)(lrow * (ASTR * 2) + (cbase + i * 8) * 2);
                CP_ASYNC16(dst + so,         qh + base + DD + i * 8);
                CP_ASYNC16(dst + 18432 + so, ql + base + DD + i * 8);
                CP_ASYNC16(dst + 36864 + so, qh + base + 2 * DD + i * 8);
                CP_ASYNC16(dst + 55296 + so, ql + base + 2 * DD + i * 8);
            }
            CP_COMMIT();
        }

        const uint32_t sK = sb + SM_ST0 + stage * STAGE_B;
        const uint32_t sV = sK + 36864;

        // ---- S = Q K^T ----
        float c[16][4];
        #pragma unroll
        for (int j = 0; j < 16; j++)
            #pragma unroll
            for (int x = 0; x < 4; x++) c[j][x] = 0.0f;

        #pragma unroll
        for (int ks = 0; ks < 4; ks++) {
            #pragma unroll
            for (int jp = 0; jp < 8; jp++) {
                uint32_t off = (uint32_t)((jp * 16 + brow_l) * ASTR + ks * 16 + bcol_l) * 2;
                uint32_t kh[4], kl[4];
                ldsm_x4(kh, sK + off);
                ldsm_x4(kl, sK + 18432 + off);
                mma16816(c[2 * jp],     aQh[ks], &kh[0]);
                mma16816(c[2 * jp],     aQh[ks], &kl[0]);
                mma16816(c[2 * jp],     aQl[ks], &kh[0]);
                mma16816(c[2 * jp + 1], aQh[ks], &kh[2]);
                mma16816(c[2 * jp + 1], aQh[ks], &kl[2]);
                mma16816(c[2 * jp + 1], aQl[ks], &kh[2]);
            }
        }

        // ---- online softmax (rows g and g+8; intra-warp reduce) ----
        float mx0 = c[0][0], mx1 = c[0][2];
        #pragma unroll
        for (int j = 0; j < 16; j++) {
            mx0 = fmaxf(mx0, fmaxf(c[j][0], c[j][1]));
            mx1 = fmaxf(mx1, fmaxf(c[j][2], c[j][3]));
        }
        mx0 = fmaxf(mx0, __shfl_xor_sync(0xffffffffu, mx0, 1));
        mx0 = fmaxf(mx0, __shfl_xor_sync(0xffffffffu, mx0, 2));
        mx1 = fmaxf(mx1, __shfl_xor_sync(0xffffffffu, mx1, 1));
        mx1 = fmaxf(mx1, __shfl_xor_sync(0xffffffffu, mx1, 2));

        float mn0 = fmaxf(m0v, mx0), mn1 = fmaxf(m1v, mx1);
        float sc0 = __expf(m0v - mn0), sc1 = __expf(m1v - mn1);
        float sum0 = 0.0f, sum1 = 0.0f;
        #pragma unroll
        for (int j = 0; j < 16; j++) {
            c[j][0] = __expf(c[j][0] - mn0); sum0 += c[j][0];
            c[j][1] = __expf(c[j][1] - mn0); sum0 += c[j][1];
            c[j][2] = __expf(c[j][2] - mn1); sum1 += c[j][2];
            c[j][3] = __expf(c[j][3] - mn1); sum1 += c[j][3];
        }
        sum0 += __shfl_xor_sync(0xffffffffu, sum0, 1);
        sum0 += __shfl_xor_sync(0xffffffffu, sum0, 2);
        sum1 += __shfl_xor_sync(0xffffffffu, sum1, 1);
        sum1 += __shfl_xor_sync(0xffffffffu, sum1, 2);
        l0v = l0v * sc0 + sum0;  m0v = mn0;
        l1v = l1v * sc1 + sum1;  m1v = mn1;
        #pragma unroll
        for (int j = 0; j < 8; j++) {
            O[j][0] *= sc0; O[j][1] *= sc0; O[j][2] *= sc1; O[j][3] *= sc1;
        }

        // ---- O += P V  (V fragments via ldmatrix.trans) ----
        #pragma unroll
        for (int kk = 0; kk < 8; kk++) {
            uint32_t ph[4], pl[4];
            split2(c[2 * kk][0],     c[2 * kk][1],     ph[0], pl[0]);
            split2(c[2 * kk][2],     c[2 * kk][3],     ph[1], pl[1]);
            split2(c[2 * kk + 1][0], c[2 * kk + 1][1], ph[2], pl[2]);
            split2(c[2 * kk + 1][2], c[2 * kk + 1][3], ph[3], pl[3]);
            #pragma unroll
            for (int jnp = 0; jnp < 4; jnp++) {
                uint32_t off = (uint32_t)((kk * 16 + vrow_l) * ASTR + jnp * 16 + vcol_l) * 2;
                uint32_t vh[4], vl[4];
                ldsm_x4_t(vh, sV + off);
                ldsm_x4_t(vl, sV + 18432 + off);
                mma16816(O[2 * jnp],     ph, &vh[0]);
                mma16816(O[2 * jnp],     ph, &vl[0]);
                mma16816(O[2 * jnp],     pl, &vh[0]);
                mma16816(O[2 * jnp + 1], ph, &vh[2]);
                mma16816(O[2 * jnp + 1], ph, &vl[2]);
                mma16816(O[2 * jnp + 1], pl, &vh[2]);
            }
        }
    }

    // Epilogue: normalize, split, write bf16 hi/lo into proj-A buffers
    float inv0 = 1.0f / l0v, inv1 = 1.0f / l1v;
    size_t r0 = (size_t)(b * TT + t0 + wq + g);
    size_t col = h * HD + tg * 2;
    #pragma unroll
    for (int jn = 0; jn < 8; jn++) {
        uint32_t h01, l01, h23, l23;
        split2(O[jn][0] * inv0, O[jn][1] * inv0, h01, l01);
        split2(O[jn][2] * inv1, O[jn][3] * inv1, h23, l23);
        size_t o0 = r0 * DD + col + jn * 8;
        size_t o1 = (r0 + 8) * DD + col + jn * 8;
        *(uint32_t*)(oh + o0) = h01;
        *(uint32_t*)(ol + o0) = l01;
        *(uint32_t*)(oh + o1) = h23;
        *(uint32_t*)(ol + o1) = l23;
    }
}

// ---------------------------------------------------------------------------
// kernel_launch
// ---------------------------------------------------------------------------
extern "C" void kernel_launch(void* const* d_in, const int* in_sizes, int n_in,
                              void* d_out, int out_size) {
    const float* x      = (const float*)d_in[0];
    const float* w_qkv  = (const float*)d_in[1];
    const float* w_proj = (const float*)d_in[2];
    float* out = (float*)d_out;

    __nv_bfloat16 *qh, *ql, *ah, *al, *bh, *bl;
    cudaGetSymbolAddress((void**)&qh, g_qh);
    cudaGetSymbolAddress((void**)&ql, g_ql);
    cudaGetSymbolAddress((void**)&ah, g_ah);
    cudaGetSymbolAddress((void**)&al, g_al);
    cudaGetSymbolAddress((void**)&bh, g_bh);
    cudaGetSymbolAddress((void**)&bl, g_bl);

    const int gemm_smem = 2 * STG * 2;
    cudaFuncSetAttribute(gemm_mma<true>,  cudaFuncAttributeMaxDynamicSharedMemorySize, gemm_smem);
    cudaFuncSetAttribute(gemm_mma<false>, cudaFuncAttributeMaxDynamicSharedMemorySize, gemm_smem);
    cudaFuncSetAttribute(attn_mma, cudaFuncAttributeMaxDynamicSharedMemorySize, ATTN_SMEM);

    const int n_act = BT * DD;

    split_kernel<<<n_act / 1024, 256>>>(x, ah, al, n_act);
    transpose_split<<<dim3(D3 / 32, DD / 32), 256>>>(w_qkv, bh, bl, DD, D3);
    gemm_mma<true><<<dim3(D3 / 128, BT / 128), 256, gemm_smem>>>(
        ah, al, bh, bl, nullptr, qh, ql, D3, DD);
    attn_mma<<<dim3(TT / 128, HH, BB), 256, ATTN_SMEM>>>(qh, ql, ah, al);
    transpose_split<<<dim3(DD / 32, DD / 32), 256>>>(w_proj, bh, bl, DD, DD);
    gemm_mma<false><<<dim3(DD / 128, BT / 128), 256, gemm_smem>>>(
        ah, al, bh, bl, out, nullptr, nullptr, DD, DD);
}

// round 12
// speedup vs baseline: 2.8128x; 1.0764x over previous
#include <cuda_runtime.h>
#include <cuda_fp16.h>
#include <math.h>
#include <stdint.h>

// Problem constants
#define BB   4
#define TT   2048
#define DD   1024
#define HH   16
#define HD   64
#define BT   (BB * TT)        // 8192
#define D3   (3 * DD)         // 3072

// Scratch (allocation-free rule: __device__ globals)
__device__ __half g_qh[BT * D3];     // qkv hi [8192][3072]
__device__ __half g_ql[BT * D3];     // qkv lo
__device__ __half g_ah[BT * DD];     // activation hi (x-split, then attn out)
__device__ __half g_al[BT * DD];     // activation lo
__device__ __half g_bh[DD * D3];     // weight^T hi
__device__ __half g_bl[DD * D3];     // weight^T lo

__device__ __forceinline__ uint32_t smem_u32(const void* p) {
    uint32_t a;
    asm("{ .reg .u64 t; cvta.to.shared.u64 t, %1; cvt.u32.u64 %0, t; }" : "=r"(a) : "l"(p));
    return a;
}

#define CP_ASYNC16(saddr, gptr) \
    asm volatile("cp.async.cg.shared.global [%0], [%1], 16;" :: "r"(saddr), "l"(gptr) : "memory")
#define CP_COMMIT() asm volatile("cp.async.commit_group;" ::: "memory")
#define CP_WAIT1()  asm volatile("cp.async.wait_group 1;" ::: "memory")
#define CP_WAIT0()  asm volatile("cp.async.wait_group 0;" ::: "memory")

__device__ __forceinline__ void mma16816(float* c, const uint32_t* a, const uint32_t* b) {
    asm volatile(
        "mma.sync.aligned.m16n8k16.row.col.f32.f16.f16.f32 "
        "{%0,%1,%2,%3}, {%4,%5,%6,%7}, {%8,%9}, {%0,%1,%2,%3};"
        : "+f"(c[0]), "+f"(c[1]), "+f"(c[2]), "+f"(c[3])
        : "r"(a[0]), "r"(a[1]), "r"(a[2]), "r"(a[3]), "r"(b[0]), "r"(b[1]));
}

__device__ __forceinline__ void ldsm_x4(uint32_t* r, uint32_t addr) {
    asm volatile("ldmatrix.sync.aligned.m8n8.x4.shared.b16 {%0,%1,%2,%3}, [%4];"
                 : "=r"(r[0]), "=r"(r[1]), "=r"(r[2]), "=r"(r[3]) : "r"(addr));
}
__device__ __forceinline__ void ldsm_x4_t(uint32_t* r, uint32_t addr) {
    asm volatile("ldmatrix.sync.aligned.m8n8.x4.trans.shared.b16 {%0,%1,%2,%3}, [%4];"
                 : "=r"(r[0]), "=r"(r[1]), "=r"(r[2]), "=r"(r[3]) : "r"(addr));
}

__device__ __forceinline__ void split2(float a, float b, uint32_t& h, uint32_t& l) {
    __half ha = __float2half_rn(a), hb = __float2half_rn(b);
    __half la = __float2half_rn(a - __half2float(ha));
    __half lb = __float2half_rn(b - __half2float(hb));
    __half2 H(ha, hb), L(la, lb);
    h = *(uint32_t*)&H; l = *(uint32_t*)&L;
}
__device__ __forceinline__ uint32_t pack2(float a, float b) {
    __half2 t = __floats2half2_rn(a, b);   // low = a, high = b
    return *(uint32_t*)&t;
}

// ---------------------------------------------------------------------------
// fp32 -> (hi, lo) fp16 split, elementwise.
// ---------------------------------------------------------------------------
__global__ __launch_bounds__(256)
void split_kernel(const float* __restrict__ in, __half* __restrict__ hi,
                  __half* __restrict__ lo, int n) {
    int i = (blockIdx.x * 256 + threadIdx.x) * 4;
    if (i >= n) return;
    float4 v = *(const float4*)(in + i);
    uint32_t h0, l0, h1, l1;
    split2(v.x, v.y, h0, l0);
    split2(v.z, v.w, h1, l1);
    uint32_t* hp = (uint32_t*)(hi + i);
    uint32_t* lp = (uint32_t*)(lo + i);
    hp[0] = h0; hp[1] = h1; lp[0] = l0; lp[1] = l1;
}

// ---------------------------------------------------------------------------
// W [K,N] fp32 row-major -> Wt hi/lo [N,K] fp16 row-major (transpose + split)
// ---------------------------------------------------------------------------
__global__ __launch_bounds__(256)
void transpose_split(const float* __restrict__ W, __half* __restrict__ Th,
                     __half* __restrict__ Tl, int K, int N) {
    __shared__ float t[32][33];
    const int k0 = blockIdx.y * 32, n0 = blockIdx.x * 32;
    const int tx = threadIdx.x & 31, ty = threadIdx.x >> 5;
    #pragma unroll
    for (int i = 0; i < 32; i += 8)
        t[ty + i][tx] = W[(size_t)(k0 + ty + i) * N + n0 + tx];
    __syncthreads();
    #pragma unroll
    for (int i = 0; i < 32; i += 8) {
        float v = t[tx][ty + i];
        __half h = __float2half_rn(v);
        size_t o = (size_t)(n0 + ty + i) * K + k0 + tx;
        Th[o] = h;
        Tl[o] = __float2half_rn(v - __half2float(h));
    }
}

// ---------------------------------------------------------------------------
// mma.sync fp16 split-GEMM (3-term, fp32-equivalent), ldmatrix fragments.
// ---------------------------------------------------------------------------
#define TS   (128 * 40)
#define STG  (4 * TS)

template <bool SPLIT_OUT>
__global__ __launch_bounds__(256)
void gemm_mma(const __half* __restrict__ Ah, const __half* __restrict__ Al,
              const __half* __restrict__ Bh, const __half* __restrict__ Bl,
              float* __restrict__ C, __half* __restrict__ Ch,
              __half* __restrict__ Cl, int N, int K) {
    extern __shared__ __align__(16) __half sm[];
    const uint32_t sb = smem_u32(sm);

    const int tid  = threadIdx.x;
    const int wid  = tid >> 5;
    const int lane = tid & 31;
    const int g    = lane >> 2;
    const int tg   = lane & 3;
    const int wm   = (wid >> 1) * 32;
    const int wn   = (wid & 1) * 64;
    const int m0   = blockIdx.y * 128;
    const int n0   = blockIdx.x * 128;

    const int arow_l = ((lane >> 3) & 1) * 8 + (lane & 7);
    const int acol_l = (lane >> 4) * 8;
    const int brow_l = ((lane >> 4) & 1) * 8 + (lane & 7);
    const int bcol_l = ((lane >> 3) & 1) * 8;

    float acc[2][8][4];
    #pragma unroll
    for (int i = 0; i < 2; i++)
        #pragma unroll
        for (int j = 0; j < 8; j++)
            #pragma unroll
            for (int c = 0; c < 4; c++) acc[i][j][c] = 0.0f;

    const int KT = K >> 5;

    auto issue = [&](int stage, int kt) {
        const int k0 = kt * 32;
        uint32_t sbase = sb + stage * STG * 2;
        #pragma unroll
        for (int h = 0; h < 2; h++) {
            int c   = tid + h * 256;
            int row = c >> 2;
            int cc  = c & 3;
            size_t ga = (size_t)(m0 + row) * K + k0 + cc * 8;
            size_t gb = (size_t)(n0 + row) * K + k0 + cc * 8;
            uint32_t so = (uint32_t)(row * 80 + cc * 16);
            CP_ASYNC16(sbase + so,          Ah + ga);
            CP_ASYNC16(sbase + TS * 2 + so, Al + ga);
            CP_ASYNC16(sbase + TS * 4 + so, Bh + gb);
            CP_ASYNC16(sbase + TS * 6 + so, Bl + gb);
        }
        CP_COMMIT();
    };

    issue(0, 0);

    for (int kt = 0; kt < KT; kt++) {
        const int stage = kt & 1;
        if (kt + 1 < KT) { issue(stage ^ 1, kt + 1); CP_WAIT1(); }
        else             { CP_WAIT0(); }
        __syncthreads();

        const uint32_t sAh = sb + stage * STG * 2;
        const uint32_t sAl = sAh + TS * 2;
        const uint32_t sBh = sAh + TS * 4;
        const uint32_t sBl = sAh + TS * 6;

        #pragma unroll
        for (int ks = 0; ks < 32; ks += 16) {
            uint32_t ah[2][4], al[2][4], bh[4][4], bl[4][4];
            #pragma unroll
            for (int i = 0; i < 2; i++) {
                uint32_t off = (uint32_t)((wm + i * 16 + arow_l) * 40 + ks + acol_l) * 2;
                ldsm_x4(ah[i], sAh + off);
                ldsm_x4(al[i], sAl + off);
            }
            #pragma unroll
            for (int jp = 0; jp < 4; jp++) {
                uint32_t off = (uint32_t)((wn + jp * 16 + brow_l) * 40 + ks + bcol_l) * 2;
                ldsm_x4(bh[jp], sBh + off);
                ldsm_x4(bl[jp], sBl + off);
            }
            #pragma unroll
            for (int i = 0; i < 2; i++)
                #pragma unroll
                for (int jp = 0; jp < 4; jp++) {
                    mma16816(acc[i][2 * jp],     ah[i], &bh[jp][0]);
                    mma16816(acc[i][2 * jp],     ah[i], &bl[jp][0]);
                    mma16816(acc[i][2 * jp],     al[i], &bh[jp][0]);
                    mma16816(acc[i][2 * jp + 1], ah[i], &bh[jp][2]);
                    mma16816(acc[i][2 * jp + 1], ah[i], &bl[jp][2]);
                    mma16816(acc[i][2 * jp + 1], al[i], &bh[jp][2]);
                }
        }
        __syncthreads();
    }

    #pragma unroll
    for (int i = 0; i < 2; i++) {
        int r0 = m0 + wm + i * 16 + g;
        #pragma unroll
        for (int j = 0; j < 8; j++) {
            int cc = n0 + wn + j * 8 + tg * 2;
            if constexpr (SPLIT_OUT) {
                uint32_t h01, l01, h23, l23;
                split2(acc[i][j][0], acc[i][j][1], h01, l01);
                split2(acc[i][j][2], acc[i][j][3], h23, l23);
                *(uint32_t*)(Ch + (size_t)r0 * N + cc)       = h01;
                *(uint32_t*)(Cl + (size_t)r0 * N + cc)       = l01;
                *(uint32_t*)(Ch + (size_t)(r0 + 8) * N + cc) = h23;
                *(uint32_t*)(Cl + (size_t)(r0 + 8) * N + cc) = l23;
            } else {
                *(float2*)(C + (size_t)r0 * N + cc)       = make_float2(acc[i][j][0], acc[i][j][1]);
                *(float2*)(C + (size_t)(r0 + 8) * N + cc) = make_float2(acc[i][j][2], acc[i][j][3]);
            }
        }
    }
}

// ---------------------------------------------------------------------------
// Flash attention, fp16 mma + ldmatrix, half-tile softmax/MMA overlap.
// S: 3-term split.  PV: P single fp16, V hi/lo -> 2 terms.
// Per tile: S0-MMA, S1-MMA, softmax0 (overlaps S1), PV0, softmax1 (overlaps PV0), PV1.
// smem: Qh 0 | Ql 18432 | stage s at 36864+s*73728: Kh|Kl|Vh|Vl (18432 each).
// ---------------------------------------------------------------------------
#define ASTR 72
#define SM_ST0 36864
#define STAGE_B 73728
#define ATTN_SMEM 184320

__global__ __launch_bounds__(256, 1)
void attn_mma(const __half* __restrict__ qh, const __half* __restrict__ ql,
              __half* __restrict__ oh, __half* __restrict__ ol) {
    extern __shared__ __align__(16) char smc[];
    const uint32_t sb = smem_u32(smc);

    const int tid  = threadIdx.x;
    const int wid  = tid >> 5;
    const int lane = tid & 31;
    const int g    = lane >> 2;
    const int tg   = lane & 3;
    const int wq   = wid * 16;
    const int qb   = blockIdx.x;
    const int h    = blockIdx.y;
    const int b    = blockIdx.z;
    const int t0   = qb * 128;

    const int lrow  = tid >> 1;
    const int cbase = (tid & 1) * 32;

    const int arow_l = ((lane >> 3) & 1) * 8 + (lane & 7);
    const int acol_l = (lane >> 4) * 8;
    const int brow_l = ((lane >> 4) & 1) * 8 + (lane & 7);
    const int bcol_l = ((lane >> 3) & 1) * 8;
    const int vrow_l = ((lane >> 3) & 1) * 8 + (lane & 7);
    const int vcol_l = ((lane >> 4) & 1) * 8;

    // Prologue: Q + K(0) + V(0) via cp.async
    {
        const size_t qgrow = ((size_t)(b * TT + t0) + lrow) * D3 + h * HD + cbase;
        const size_t base0 = ((size_t)(b * TT) + lrow) * D3 + h * HD + cbase;
        #pragma unroll
        for (int i = 0; i < 4; i++) {
            uint32_t so = (uint32_t)(lrow * (ASTR * 2) + (cbase + i * 8) * 2);
            CP_ASYNC16(sb + so,         qh + qgrow + i * 8);
            CP_ASYNC16(sb + 18432 + so, ql + qgrow + i * 8);
            CP_ASYNC16(sb + SM_ST0 + so,         qh + base0 + DD + i * 8);
            CP_ASYNC16(sb + SM_ST0 + 18432 + so, ql + base0 + DD + i * 8);
            CP_ASYNC16(sb + SM_ST0 + 36864 + so, qh + base0 + 2 * DD + i * 8);
            CP_ASYNC16(sb + SM_ST0 + 55296 + so, ql + base0 + 2 * DD + i * 8);
        }
        CP_COMMIT();
    }
    CP_WAIT0();
    __syncthreads();

    // Q fragments (persistent)
    uint32_t aQh[4][4], aQl[4][4];
    #pragma unroll
    for (int ks = 0; ks < 4; ks++) {
        uint32_t off = (uint32_t)((wq + arow_l) * ASTR + ks * 16 + acol_l) * 2;
        ldsm_x4(aQh[ks], sb + off);
        ldsm_x4(aQl[ks], sb + 18432 + off);
    }

    float O[8][4];
    #pragma unroll
    for (int j = 0; j < 8; j++)
        #pragma unroll
        for (int c = 0; c < 4; c++) O[j][c] = 0.0f;
    float m0v = -1e30f, m1v = -1e30f, l0v = 0.0f, l1v = 0.0f;

    const int NT = TT / 128;
    for (int kv = 0; kv < NT; kv++) {
        const int stage = kv & 1;
        if (kv > 0) { CP_WAIT0(); __syncthreads(); }

        if (kv + 1 < NT) {
            const size_t base = ((size_t)(b * TT + (kv + 1) * 128) + lrow) * D3 + h * HD + cbase;
            uint32_t dst = sb + SM_ST0 + (stage ^ 1) * STAGE_B;
            #pragma unroll
            for (int i = 0; i < 4; i++) {
                uint32_t so = (uint32_t)(lrow * (ASTR * 2) + (cbase + i * 8) * 2);
                CP_ASYNC16(dst + so,         qh + base + DD + i * 8);
                CP_ASYNC16(dst + 18432 + so, ql + base + DD + i * 8);
                CP_ASYNC16(dst + 36864 + so, qh + base + 2 * DD + i * 8);
                CP_ASYNC16(dst + 55296 + so, ql + base + 2 * DD + i * 8);
            }
            CP_COMMIT();
        }

        const uint32_t sK = sb + SM_ST0 + stage * STAGE_B;
        const uint32_t sV = sK + 36864;

        float c[16][4];
        #pragma unroll
        for (int j = 0; j < 16; j++)
            #pragma unroll
            for (int x = 0; x < 4; x++) c[j][x] = 0.0f;

        // ---- S-MMA, both halves back-to-back (fills tensor pipe) ----
        #pragma unroll
        for (int half = 0; half < 2; half++) {
            #pragma unroll
            for (int ks = 0; ks < 4; ks++) {
                #pragma unroll
                for (int jp = 4 * half; jp < 4 * half + 4; jp++) {
                    uint32_t off = (uint32_t)((jp * 16 + brow_l) * ASTR + ks * 16 + bcol_l) * 2;
                    uint32_t kh[4], kl[4];
                    ldsm_x4(kh, sK + off);
                    ldsm_x4(kl, sK + 18432 + off);
                    mma16816(c[2 * jp],     aQh[ks], &kh[0]);
                    mma16816(c[2 * jp],     aQh[ks], &kl[0]);
                    mma16816(c[2 * jp],     aQl[ks], &kh[0]);
                    mma16816(c[2 * jp + 1], aQh[ks], &kh[2]);
                    mma16816(c[2 * jp + 1], aQh[ks], &kl[2]);
                    mma16816(c[2 * jp + 1], aQl[ks], &kh[2]);
                }
            }
        }

        // ---- interleaved: softmax(half) then PV(half) ----
        #pragma unroll
        for (int half = 0; half < 2; half++) {
            const int jb = 8 * half;
            // softmax for this half's 64 cols (overlaps prior MMAs in pipe)
            float mx0 = c[jb][0], mx1 = c[jb][2];
            #pragma unroll
            for (int j = jb; j < jb + 8; j++) {
                mx0 = fmaxf(mx0, fmaxf(c[j][0], c[j][1]));
                mx1 = fmaxf(mx1, fmaxf(c[j][2], c[j][3]));
            }
            mx0 = fmaxf(mx0, __shfl_xor_sync(0xffffffffu, mx0, 1));
            mx0 = fmaxf(mx0, __shfl_xor_sync(0xffffffffu, mx0, 2));
            mx1 = fmaxf(mx1, __shfl_xor_sync(0xffffffffu, mx1, 1));
            mx1 = fmaxf(mx1, __shfl_xor_sync(0xffffffffu, mx1, 2));

            float mn0 = fmaxf(m0v, mx0), mn1 = fmaxf(m1v, mx1);
            float sc0 = __expf(m0v - mn0), sc1 = __expf(m1v - mn1);
            float sum0 = 0.0f, sum1 = 0.0f;
            #pragma unroll
            for (int j = jb; j < jb + 8; j++) {
                c[j][0] = __expf(c[j][0] - mn0); sum0 += c[j][0];
                c[j][1] = __expf(c[j][1] - mn0); sum0 += c[j][1];
                c[j][2] = __expf(c[j][2] - mn1); sum1 += c[j][2];
                c[j][3] = __expf(c[j][3] - mn1); sum1 += c[j][3];
            }
            sum0 += __shfl_xor_sync(0xffffffffu, sum0, 1);
            sum0 += __shfl_xor_sync(0xffffffffu, sum0, 2);
            sum1 += __shfl_xor_sync(0xffffffffu, sum1, 1);
            sum1 += __shfl_xor_sync(0xffffffffu, sum1, 2);
            l0v = l0v * sc0 + sum0;  m0v = mn0;
            l1v = l1v * sc1 + sum1;  m1v = mn1;
            #pragma unroll
            for (int j = 0; j < 8; j++) {
                O[j][0] *= sc0; O[j][1] *= sc0; O[j][2] *= sc1; O[j][3] *= sc1;
            }

            // PV for this half: P single fp16, V hi/lo -> 2 MMAs per frag
            #pragma unroll
            for (int kk = 4 * half; kk < 4 * half + 4; kk++) {
                uint32_t p[4];
                p[0] = pack2(c[2 * kk][0],     c[2 * kk][1]);
                p[1] = pack2(c[2 * kk][2],     c[2 * kk][3]);
                p[2] = pack2(c[2 * kk + 1][0], c[2 * kk + 1][1]);
                p[3] = pack2(c[2 * kk + 1][2], c[2 * kk + 1][3]);
                #pragma unroll
                for (int jnp = 0; jnp < 4; jnp++) {
                    uint32_t off = (uint32_t)((kk * 16 + vrow_l) * ASTR + jnp * 16 + vcol_l) * 2;
                    uint32_t vh[4], vl[4];
                    ldsm_x4_t(vh, sV + off);
                    ldsm_x4_t(vl, sV + 18432 + off);
                    mma16816(O[2 * jnp],     p, &vh[0]);
                    mma16816(O[2 * jnp],     p, &vl[0]);
                    mma16816(O[2 * jnp + 1], p, &vh[2]);
                    mma16816(O[2 * jnp + 1], p, &vl[2]);
                }
            }
        }
    }

    // Epilogue: normalize, split, write fp16 hi/lo into proj-A buffers
    float inv0 = 1.0f / l0v, inv1 = 1.0f / l1v;
    size_t r0 = (size_t)(b * TT + t0 + wq + g);
    size_t col = h * HD + tg * 2;
    #pragma unroll
    for (int jn = 0; jn < 8; jn++) {
        uint32_t h01, l01, h23, l23;
        split2(O[jn][0] * inv0, O[jn][1] * inv0, h01, l01);
        split2(O[jn][2] * inv1, O[jn][3] * inv1, h23, l23);
        size_t o0 = r0 * DD + col + jn * 8;
        size_t o1 = (r0 + 8) * DD + col + jn * 8;
        *(uint32_t*)(oh + o0) = h01;
        *(uint32_t*)(ol + o0) = l01;
        *(uint32_t*)(oh + o1) = h23;
        *(uint32_t*)(ol + o1) = l23;
    }
}

// ---------------------------------------------------------------------------
// kernel_launch
// ---------------------------------------------------------------------------
extern "C" void kernel_launch(void* const* d_in, const int* in_sizes, int n_in,
                              void* d_out, int out_size) {
    const float* x      = (const float*)d_in[0];
    const float* w_qkv  = (const float*)d_in[1];
    const float* w_proj = (const float*)d_in[2];
    float* out = (float*)d_out;

    __half *qh, *ql, *ah, *al, *bh, *bl;
    cudaGetSymbolAddress((void**)&qh, g_qh);
    cudaGetSymbolAddress((void**)&ql, g_ql);
    cudaGetSymbolAddress((void**)&ah, g_ah);
    cudaGetSymbolAddress((void**)&al, g_al);
    cudaGetSymbolAddress((void**)&bh, g_bh);
    cudaGetSymbolAddress((void**)&bl, g_bl);

    const int gemm_smem = 2 * STG * 2;
    cudaFuncSetAttribute(gemm_mma<true>,  cudaFuncAttributeMaxDynamicSharedMemorySize, gemm_smem);
    cudaFuncSetAttribute(gemm_mma<false>, cudaFuncAttributeMaxDynamicSharedMemorySize, gemm_smem);
    cudaFuncSetAttribute(attn_mma, cudaFuncAttributeMaxDynamicSharedMemorySize, ATTN_SMEM);

    const int n_act = BT * DD;

    split_kernel<<<n_act / 1024, 256>>>(x, ah, al, n_act);
    transpose_split<<<dim3(D3 / 32, DD / 32), 256>>>(w_qkv, bh, bl, DD, D3);
    gemm_mma<true><<<dim3(D3 / 128, BT / 128), 256, gemm_smem>>>(
        ah, al, bh, bl, nullptr, qh, ql, D3, DD);
    attn_mma<<<dim3(TT / 128, HH, BB), 256, ATTN_SMEM>>>(qh, ql, ah, al);
    transpose_split<<<dim3(DD / 32, DD / 32), 256>>>(w_proj, bh, bl, DD, DD);
    gemm_mma<false><<<dim3(DD / 128, BT / 128), 256, gemm_smem>>>(
        ah, al, bh, bl, out, nullptr, nullptr, DD, DD);
}